// round 1
// baseline (speedup 1.0000x reference)
#include <cuda_runtime.h>
#include <cuda_bf16.h>
#include <cstdint>

// Problem constants
constexpr int Bc  = 2;
constexpr int Sc  = 2048;
constexpr int Dm  = 1024;
constexpr int Hn  = 16;
constexpr int DKc = 64;
constexpr int Mr  = Bc * Sc;      // 4096

// Scratch (device globals; allocation in kernel_launch is forbidden)
__device__ float g_Q[(size_t)Bc * Hn * Sc * DKc];   // [B*H, S, 64]
__device__ float g_K[(size_t)Bc * Hn * Sc * DKc];
__device__ float g_V[(size_t)Bc * Hn * Sc * DKc];
__device__ float g_A[(size_t)Bc * Sc * Dm];         // attention output, [B, S, D]

// ---------------------------------------------------------------------------
// 128x128x16 fp32 GEMM:  out[m,n] = sum_k X[m,k] * W[n,k] + bias[n]
// (i.e. y = X @ W^T + b, torch Linear convention)
// split_heads: write out in [B*H, S, 64] layout instead of [M, N].
// ---------------------------------------------------------------------------
__global__ __launch_bounds__(256) void gemm128(
    const float* __restrict__ X, const float* __restrict__ W,
    const float* __restrict__ bias, float* __restrict__ out, int split_heads)
{
    __shared__ float As[16][132];
    __shared__ float Bs[16][132];

    const int tid = threadIdx.x;
    const int m0  = blockIdx.y * 128;
    const int n0  = blockIdx.x * 128;

    const int lr = tid >> 2;         // 0..63
    const int lc = (tid & 3) << 2;   // 0,4,8,12
    const int tx = tid & 15;
    const int ty = tid >> 4;

    float acc[8][8] = {};

    for (int k0 = 0; k0 < Dm; k0 += 16) {
        #pragma unroll
        for (int p = 0; p < 2; p++) {
            const int r = lr + p * 64;
            float4 va = *(const float4*)(X + (size_t)(m0 + r) * Dm + k0 + lc);
            As[lc + 0][r] = va.x; As[lc + 1][r] = va.y;
            As[lc + 2][r] = va.z; As[lc + 3][r] = va.w;
            float4 vb = *(const float4*)(W + (size_t)(n0 + r) * Dm + k0 + lc);
            Bs[lc + 0][r] = vb.x; Bs[lc + 1][r] = vb.y;
            Bs[lc + 2][r] = vb.z; Bs[lc + 3][r] = vb.w;
        }
        __syncthreads();

        #pragma unroll
        for (int kk = 0; kk < 16; kk++) {
            float a[8], b[8];
            #pragma unroll
            for (int i = 0; i < 8; i++) a[i] = As[kk][ty * 8 + i];
            #pragma unroll
            for (int j = 0; j < 8; j++) b[j] = Bs[kk][tx * 8 + j];
            #pragma unroll
            for (int i = 0; i < 8; i++)
                #pragma unroll
                for (int j = 0; j < 8; j++)
                    acc[i][j] = fmaf(a[i], b[j], acc[i][j]);
        }
        __syncthreads();
    }

    #pragma unroll
    for (int i = 0; i < 8; i++) {
        const int m = m0 + ty * 8 + i;
        #pragma unroll
        for (int j = 0; j < 8; j++) {
            const int n = n0 + tx * 8 + j;
            const float v = acc[i][j] + bias[n];
            if (split_heads) {
                const int bb = m >> 11, ss = m & 2047;
                const int hh = n >> 6,  dd = n & 63;
                out[(((size_t)(bb * Hn + hh)) * Sc + ss) * DKc + dd] = v;
            } else {
                out[(size_t)m * Dm + n] = v;
            }
        }
    }
}

// ---------------------------------------------------------------------------
// Flash attention (causal), fp32. One thread per query row; 128 rows/block.
// Q/K/V in [B*H, S, 64]. Output written into g_A in [B, S, D] layout.
// ---------------------------------------------------------------------------
__global__ __launch_bounds__(128) void attn_kernel(float* __restrict__ attn_out)
{
    __shared__ float Ks[32][64];
    __shared__ float Vs[32][64];

    const int tid = threadIdx.x;
    const int q0  = blockIdx.x * 128;
    const int bh  = blockIdx.y;                     // 0..31
    const float* Qp = g_Q + (size_t)bh * Sc * DKc;
    const float* Kp = g_K + (size_t)bh * Sc * DKc;
    const float* Vp = g_V + (size_t)bh * Sc * DKc;
    const int qi = q0 + tid;

    float q[64];
    #pragma unroll
    for (int k = 0; k < 64; k += 4) {
        float4 v = *(const float4*)(Qp + (size_t)qi * 64 + k);
        q[k] = v.x; q[k + 1] = v.y; q[k + 2] = v.z; q[k + 3] = v.w;
    }

    float o[64] = {};
    float mrow = -1e30f, lrow = 0.f;

    for (int j0 = 0; j0 < q0 + 128; j0 += 32) {
        // Stage K/V tile (32x64 each). 512 float4 per tile, 4 per thread.
        #pragma unroll
        for (int t = 0; t < 4; t++) {
            const int idx = tid + t * 128;       // float4 index 0..511
            const int row = idx >> 4;
            const int col = (idx & 15) << 2;
            *(float4*)&Ks[row][col] = *(const float4*)(Kp + (size_t)(j0 + row) * 64 + col);
            *(float4*)&Vs[row][col] = *(const float4*)(Vp + (size_t)(j0 + row) * 64 + col);
        }
        __syncthreads();

        float sv[32];
        float tmax = -1e30f;
        #pragma unroll
        for (int jj = 0; jj < 32; jj++) {
            float s = 0.f;
            #pragma unroll
            for (int k = 0; k < 64; k++) s = fmaf(q[k], Ks[jj][k], s);
            s *= 0.125f;                          // 1/sqrt(64)
            if (j0 + jj > qi) s = -1e30f;         // causal mask
            sv[jj] = s;
            tmax = fmaxf(tmax, s);
        }

        const float mnew = fmaxf(mrow, tmax);
        const float corr = __expf(mrow - mnew);
        lrow *= corr;
        #pragma unroll
        for (int d = 0; d < 64; d++) o[d] *= corr;

        #pragma unroll
        for (int jj = 0; jj < 32; jj++) {
            const float p = __expf(sv[jj] - mnew);
            lrow += p;
            #pragma unroll
            for (int d = 0; d < 64; d++) o[d] = fmaf(p, Vs[jj][d], o[d]);
        }
        mrow = mnew;
        __syncthreads();
    }

    const float inv = 1.0f / lrow;
    const int bb = bh >> 4, hh = bh & 15;
    float* dst = attn_out + ((size_t)bb * Sc + qi) * Dm + hh * 64;
    #pragma unroll
    for (int d = 0; d < 64; d += 4) {
        float4 v = make_float4(o[d] * inv, o[d + 1] * inv, o[d + 2] * inv, o[d + 3] * inv);
        *(float4*)(dst + d) = v;
    }
}

// ---------------------------------------------------------------------------
extern "C" void kernel_launch(void* const* d_in, const int* in_sizes, int n_in,
                              void* d_out, int out_size)
{
    const float* x  = (const float*)d_in[0];
    // d_in[1] = mask (int32 tril) — causal mask hardcoded in attn_kernel
    const float* Wq = (const float*)d_in[2];
    const float* bq = (const float*)d_in[3];
    const float* Wk = (const float*)d_in[4];
    const float* bk = (const float*)d_in[5];
    const float* Wv = (const float*)d_in[6];
    const float* bv = (const float*)d_in[7];
    const float* Wo = (const float*)d_in[8];
    const float* bo = (const float*)d_in[9];
    float* out = (float*)d_out;

    float *gQ, *gK, *gV, *gA;
    cudaGetSymbolAddress((void**)&gQ, g_Q);
    cudaGetSymbolAddress((void**)&gK, g_K);
    cudaGetSymbolAddress((void**)&gV, g_V);
    cudaGetSymbolAddress((void**)&gA, g_A);

    const dim3 ggrid(Dm / 128, Mr / 128);   // (8, 32)

    gemm128<<<ggrid, 256>>>(x,  Wq, bq, gQ, 1);
    gemm128<<<ggrid, 256>>>(x,  Wk, bk, gK, 1);
    gemm128<<<ggrid, 256>>>(x,  Wv, bv, gV, 1);

    attn_kernel<<<dim3(Sc / 128, Bc * Hn), 128>>>(gA);

    gemm128<<<ggrid, 256>>>(gA, Wo, bo, out, 0);
}

// round 3
// speedup vs baseline: 1.3544x; 1.3544x over previous
#include <cuda_runtime.h>
#include <cuda_bf16.h>
#include <cstdint>

// Problem constants
constexpr int Bc  = 2;
constexpr int Sc  = 2048;
constexpr int Dm  = 1024;
constexpr int Hn  = 16;
constexpr int DKc = 64;
constexpr int Mr  = Bc * Sc;      // 4096

// Scratch (device globals; allocation in kernel_launch is forbidden)
__device__ float g_Q[(size_t)Mr * Dm / 16];   // [B*H, S, 64] -> actually full size below
// (note: real sizes)
__device__ float g_Qf[(size_t)Bc * Hn * Sc * DKc];
__device__ float g_Kf[(size_t)Bc * Hn * Sc * DKc];
__device__ float g_Vf[(size_t)Bc * Hn * Sc * DKc];
__device__ float g_Af[(size_t)Bc * Sc * Dm];
__device__ __align__(16) __nv_bfloat16 g_Xh[(size_t)Mr * Dm];
__device__ __align__(16) __nv_bfloat16 g_Xl[(size_t)Mr * Dm];
__device__ __align__(16) __nv_bfloat16 g_Ah[(size_t)Mr * Dm];
__device__ __align__(16) __nv_bfloat16 g_Al[(size_t)Mr * Dm];
__device__ __align__(16) __nv_bfloat16 g_Wh[(size_t)4 * Dm * Dm];
__device__ __align__(16) __nv_bfloat16 g_Wl[(size_t)4 * Dm * Dm];

// ---------------------------------------------------------------------------
// helpers
// ---------------------------------------------------------------------------
__device__ __forceinline__ uint32_t s2u(const void* p) {
    uint32_t a;
    asm("{ .reg .u64 t; cvta.to.shared.u64 t, %1; cvt.u32.u64 %0, t; }"
        : "=r"(a) : "l"(p));
    return a;
}

__device__ __forceinline__ void cpa16(uint32_t s, const void* g) {
    asm volatile("cp.async.cg.shared.global [%0], [%1], 16;" :: "r"(s), "l"(g));
}

#define LDSM4(r0, r1, r2, r3, addr) \
    asm volatile("ldmatrix.sync.aligned.m8n8.x4.shared.b16 {%0,%1,%2,%3}, [%4];" \
        : "=r"(r0), "=r"(r1), "=r"(r2), "=r"(r3) : "r"(addr))

#define MMA_BF16(d, a, b) \
    asm volatile("mma.sync.aligned.m16n8k16.row.col.f32.bf16.bf16.f32 " \
        "{%0,%1,%2,%3}, {%4,%5,%6,%7}, {%8,%9}, {%0,%1,%2,%3};" \
        : "+f"((d)[0]), "+f"((d)[1]), "+f"((d)[2]), "+f"((d)[3]) \
        : "r"((a)[0]), "r"((a)[1]), "r"((a)[2]), "r"((a)[3]), \
          "r"((b)[0]), "r"((b)[1]))

// Stage tile: 128 rows x 32 k (bf16) stored with 80B row pitch (64B data+16B pad)
// -> ldmatrix granule index r*5+c is a full cycle mod 8: conflict-free.
constexpr int TPITCH  = 80;
constexpr int TILEB   = 128 * TPITCH;              // 10240 B
constexpr int STAGEB  = 4 * TILEB;                 // Ah, Al, Bh, Bl
constexpr int NSTAGE  = 3;
constexpr int SMEM_SZ = 1024 + NSTAGE * STAGEB;    // 123904 B

// ---------------------------------------------------------------------------
// Split-bf16 warp-MMA GEMM: out[m,n] = sum_k A[m,k]*B[n,k] + bias[n]
// D = AhBh + AhBl + AlBh, fp32 accumulators.
// ---------------------------------------------------------------------------
__global__ __launch_bounds__(256, 1) void gemm_tc(
    const __nv_bfloat16* __restrict__ Ahp, const __nv_bfloat16* __restrict__ Alp,
    const __nv_bfloat16* __restrict__ Bhp, const __nv_bfloat16* __restrict__ Blp,
    const float* __restrict__ bias, float* __restrict__ out, int split_heads)
{
    extern __shared__ char smem[];
    const uint32_t sb = s2u(smem);
    const int t   = threadIdx.x;
    const int wid = t >> 5, l = t & 31;
    const int m0  = blockIdx.y * 128, n0 = blockIdx.x * 128;

    if (t < 128) ((float*)smem)[16 + t] = bias[n0 + t];

    // per-thread load slots: row = t>>2 (+64), chunk c = t&3
    const int lrow = t >> 2, lc = t & 3;
    const __nv_bfloat16* gA0 = Ahp + (size_t)(m0 + lrow) * Dm + lc * 8;
    const __nv_bfloat16* gA1 = Alp + (size_t)(m0 + lrow) * Dm + lc * 8;
    const __nv_bfloat16* gB0 = Bhp + (size_t)(n0 + lrow) * Dm + lc * 8;
    const __nv_bfloat16* gB1 = Blp + (size_t)(n0 + lrow) * Dm + lc * 8;
    const uint32_t so = (uint32_t)(lrow * TPITCH + lc * 16);

#define STAGE_LOAD(buf, kt)                                                     \
    {                                                                           \
        const uint32_t s0 = sb + 1024 + (buf) * STAGEB + so;                    \
        const int ke = (kt) * 32;                                               \
        cpa16(s0,                 gA0 + ke);                                    \
        cpa16(s0 + 64 * TPITCH,   gA0 + ke + 64 * Dm);                          \
        cpa16(s0 + TILEB,             gA1 + ke);                                \
        cpa16(s0 + TILEB + 64*TPITCH, gA1 + ke + 64 * Dm);                      \
        cpa16(s0 + 2*TILEB,             gB0 + ke);                              \
        cpa16(s0 + 2*TILEB + 64*TPITCH, gB0 + ke + 64 * Dm);                    \
        cpa16(s0 + 3*TILEB,             gB1 + ke);                              \
        cpa16(s0 + 3*TILEB + 64*TPITCH, gB1 + ke + 64 * Dm);                    \
        asm volatile("cp.async.commit_group;");                                 \
    }

    STAGE_LOAD(0, 0)
    STAGE_LOAD(1, 1)

    const int warp_m = (wid & 3) * 32;
    const int warp_n = (wid >> 2) * 64;
    // lane offsets for ldmatrix
    const int arow = warp_m + (l & 7) + ((l & 8) ? 8 : 0);
    const int akb  = (l & 16) ? 1 : 0;
    const int brow = warp_n + (l & 7) + ((l & 16) ? 8 : 0);
    const int bkb  = (l >> 3) & 1;

    float acc[2][8][4] = {};

    #pragma unroll 1
    for (int kt = 0; kt < 32; kt++) {
        asm volatile("cp.async.wait_group 1;");
        __syncthreads();
        if (kt + 2 < 32) STAGE_LOAD((kt + 2) % NSTAGE, kt + 2)

        const uint32_t st = sb + 1024 + (kt % NSTAGE) * STAGEB;
        #pragma unroll
        for (int ks = 0; ks < 2; ks++) {
            uint32_t ah[2][4], al[2][4], bh[8][2], bl[8][2];
            #pragma unroll
            for (int mt = 0; mt < 2; mt++) {
                const uint32_t ra = (uint32_t)((arow + mt * 16) * TPITCH +
                                               (ks * 2 + akb) * 16);
                LDSM4(ah[mt][0], ah[mt][1], ah[mt][2], ah[mt][3], st + ra);
                LDSM4(al[mt][0], al[mt][1], al[mt][2], al[mt][3], st + TILEB + ra);
            }
            #pragma unroll
            for (int p = 0; p < 4; p++) {
                const uint32_t rb = (uint32_t)((brow + p * 16) * TPITCH +
                                               (ks * 2 + bkb) * 16);
                LDSM4(bh[2*p][0], bh[2*p][1], bh[2*p+1][0], bh[2*p+1][1],
                      st + 2 * TILEB + rb);
                LDSM4(bl[2*p][0], bl[2*p][1], bl[2*p+1][0], bl[2*p+1][1],
                      st + 3 * TILEB + rb);
            }
            #pragma unroll
            for (int mt = 0; mt < 2; mt++)
                #pragma unroll
                for (int nt = 0; nt < 8; nt++) {
                    MMA_BF16(acc[mt][nt], ah[mt], bh[nt]);
                    MMA_BF16(acc[mt][nt], ah[mt], bl[nt]);
                    MMA_BF16(acc[mt][nt], al[mt], bh[nt]);
                }
        }
    }

    // epilogue: bias + store (optionally head-split)
    const float* bsm = (const float*)smem + 16;
    #pragma unroll
    for (int mt = 0; mt < 2; mt++) {
        #pragma unroll
        for (int nt = 0; nt < 8; nt++) {
            const int mrow = m0 + warp_m + mt * 16 + (l >> 2);
            const int ncol = n0 + warp_n + nt * 8 + (l & 3) * 2;
            const float b0 = bsm[ncol - n0], b1 = bsm[ncol - n0 + 1];
            float2 v0 = make_float2(acc[mt][nt][0] + b0, acc[mt][nt][1] + b1);
            float2 v1 = make_float2(acc[mt][nt][2] + b0, acc[mt][nt][3] + b1);
            if (split_heads) {
                const int bb = mrow >> 11, hh = ncol >> 6, dd = ncol & 63;
                float* d0 = out + (((size_t)(bb * Hn + hh)) * Sc + (mrow & 2047)) * DKc + dd;
                *(float2*)d0 = v0;
                *(float2*)(d0 + 8 * DKc) = v1;
            } else {
                float* d0 = out + (size_t)mrow * Dm + ncol;
                *(float2*)d0 = v0;
                *(float2*)(d0 + 8 * Dm) = v1;
            }
        }
    }
#undef STAGE_LOAD
}

// ---------------------------------------------------------------------------
// fp32 -> bf16 hi/lo split
// ---------------------------------------------------------------------------
__global__ __launch_bounds__(256) void cvt_split(
    const float* __restrict__ src, __nv_bfloat16* __restrict__ hi,
    __nv_bfloat16* __restrict__ lo, int n)
{
    const int i = (blockIdx.x * blockDim.x + threadIdx.x) * 4;
    if (i >= n) return;
    float4 f = *(const float4*)(src + i);
    float a[4] = {f.x, f.y, f.z, f.w};
    __nv_bfloat16 h[4], l[4];
    #pragma unroll
    for (int j = 0; j < 4; j++) {
        h[j] = __float2bfloat16(a[j]);
        l[j] = __float2bfloat16(a[j] - __bfloat162float(h[j]));
    }
    __nv_bfloat162* H = (__nv_bfloat162*)(hi + i);
    __nv_bfloat162* L = (__nv_bfloat162*)(lo + i);
    H[0] = __halves2bfloat162(h[0], h[1]);
    H[1] = __halves2bfloat162(h[2], h[3]);
    L[0] = __halves2bfloat162(l[0], l[1]);
    L[1] = __halves2bfloat162(l[2], l[3]);
}

// ---------------------------------------------------------------------------
// Flash attention (causal), fp32. One thread per query row; 128 rows/block.
// ---------------------------------------------------------------------------
__global__ __launch_bounds__(128) void attn_kernel(float* __restrict__ attn_out)
{
    __shared__ float Ks[32][64];
    __shared__ float Vs[32][64];

    const int tid = threadIdx.x;
    const int q0  = blockIdx.x * 128;
    const int bh  = blockIdx.y;                     // 0..31
    const float* Qp = g_Qf + (size_t)bh * Sc * DKc;
    const float* Kp = g_Kf + (size_t)bh * Sc * DKc;
    const float* Vp = g_Vf + (size_t)bh * Sc * DKc;
    const int qi = q0 + tid;

    float q[64];
    #pragma unroll
    for (int k = 0; k < 64; k += 4) {
        float4 v = *(const float4*)(Qp + (size_t)qi * 64 + k);
        q[k] = v.x; q[k + 1] = v.y; q[k + 2] = v.z; q[k + 3] = v.w;
    }

    float o[64] = {};
    float mrow = -1e30f, lrow = 0.f;

    for (int j0 = 0; j0 < q0 + 128; j0 += 32) {
        #pragma unroll
        for (int tcp = 0; tcp < 4; tcp++) {
            const int idx = tid + tcp * 128;
            const int row = idx >> 4;
            const int col = (idx & 15) << 2;
            *(float4*)&Ks[row][col] = *(const float4*)(Kp + (size_t)(j0 + row) * 64 + col);
            *(float4*)&Vs[row][col] = *(const float4*)(Vp + (size_t)(j0 + row) * 64 + col);
        }
        __syncthreads();

        float sv[32];
        float tmax = -1e30f;
        #pragma unroll
        for (int jj = 0; jj < 32; jj++) {
            float s = 0.f;
            #pragma unroll
            for (int k = 0; k < 64; k++) s = fmaf(q[k], Ks[jj][k], s);
            s *= 0.125f;
            if (j0 + jj > qi) s = -1e30f;
            sv[jj] = s;
            tmax = fmaxf(tmax, s);
        }

        const float mnew = fmaxf(mrow, tmax);
        const float corr = __expf(mrow - mnew);
        lrow *= corr;
        #pragma unroll
        for (int d = 0; d < 64; d++) o[d] *= corr;

        #pragma unroll
        for (int jj = 0; jj < 32; jj++) {
            const float p = __expf(sv[jj] - mnew);
            lrow += p;
            #pragma unroll
            for (int d = 0; d < 64; d++) o[d] = fmaf(p, Vs[jj][d], o[d]);
        }
        mrow = mnew;
        __syncthreads();
    }

    const float inv = 1.0f / lrow;
    const int bb = bh >> 4, hh = bh & 15;
    float* dst = attn_out + ((size_t)bb * Sc + qi) * Dm + hh * 64;
    #pragma unroll
    for (int d = 0; d < 64; d += 4) {
        float4 v = make_float4(o[d] * inv, o[d + 1] * inv, o[d + 2] * inv, o[d + 3] * inv);
        *(float4*)(dst + d) = v;
    }
}

// ---------------------------------------------------------------------------
extern "C" void kernel_launch(void* const* d_in, const int* in_sizes, int n_in,
                              void* d_out, int out_size)
{
    const float* x  = (const float*)d_in[0];
    // d_in[1] = mask (int32 tril) — causal mask hardcoded in attn_kernel
    const float* Wq = (const float*)d_in[2];
    const float* bq = (const float*)d_in[3];
    const float* Wk = (const float*)d_in[4];
    const float* bk = (const float*)d_in[5];
    const float* Wv = (const float*)d_in[6];
    const float* bv = (const float*)d_in[7];
    const float* Wo = (const float*)d_in[8];
    const float* bo = (const float*)d_in[9];
    float* out = (float*)d_out;

    float *gQ, *gK, *gV, *gA;
    __nv_bfloat16 *gXh, *gXl, *gAh, *gAl, *gWh, *gWl;
    cudaGetSymbolAddress((void**)&gQ,  g_Qf);
    cudaGetSymbolAddress((void**)&gK,  g_Kf);
    cudaGetSymbolAddress((void**)&gV,  g_Vf);
    cudaGetSymbolAddress((void**)&gA,  g_Af);
    cudaGetSymbolAddress((void**)&gXh, g_Xh);
    cudaGetSymbolAddress((void**)&gXl, g_Xl);
    cudaGetSymbolAddress((void**)&gAh, g_Ah);
    cudaGetSymbolAddress((void**)&gAl, g_Al);
    cudaGetSymbolAddress((void**)&gWh, g_Wh);
    cudaGetSymbolAddress((void**)&gWl, g_Wl);

    cudaFuncSetAttribute(gemm_tc, cudaFuncAttributeMaxDynamicSharedMemorySize, SMEM_SZ);

    const int nx = Mr * Dm;       // 4M elems
    const int nw = Dm * Dm;       // 1M elems

    cvt_split<<<nx / 4 / 256, 256>>>(x,  gXh, gXl, nx);
    cvt_split<<<nw / 4 / 256, 256>>>(Wq, gWh + 0 * (size_t)nw, gWl + 0 * (size_t)nw, nw);
    cvt_split<<<nw / 4 / 256, 256>>>(Wk, gWh + 1 * (size_t)nw, gWl + 1 * (size_t)nw, nw);
    cvt_split<<<nw / 4 / 256, 256>>>(Wv, gWh + 2 * (size_t)nw, gWl + 2 * (size_t)nw, nw);
    cvt_split<<<nw / 4 / 256, 256>>>(Wo, gWh + 3 * (size_t)nw, gWl + 3 * (size_t)nw, nw);

    const dim3 gg(Dm / 128, Mr / 128);   // (8, 32)
    gemm_tc<<<gg, 256, SMEM_SZ>>>(gXh, gXl, gWh + 0 * (size_t)nw, gWl + 0 * (size_t)nw, bq, gQ, 1);
    gemm_tc<<<gg, 256, SMEM_SZ>>>(gXh, gXl, gWh + 1 * (size_t)nw, gWl + 1 * (size_t)nw, bk, gK, 1);
    gemm_tc<<<gg, 256, SMEM_SZ>>>(gXh, gXl, gWh + 2 * (size_t)nw, gWl + 2 * (size_t)nw, bv, gV, 1);

    attn_kernel<<<dim3(Sc / 128, Bc * Hn), 128>>>(gA);

    cvt_split<<<nx / 4 / 256, 256>>>(gA, gAh, gAl, nx);
    gemm_tc<<<gg, 256, SMEM_SZ>>>(gAh, gAl, gWh + 3 * (size_t)nw, gWl + 3 * (size_t)nw, bo, out, 0);
}

// round 5
// speedup vs baseline: 3.3185x; 2.4501x over previous
#include <cuda_runtime.h>
#include <cuda_bf16.h>
#include <cstdint>

// Problem constants
constexpr int Bc  = 2;
constexpr int Sc  = 2048;
constexpr int Dm  = 1024;
constexpr int Hn  = 16;
constexpr int DKc = 64;
constexpr int Mr  = Bc * Sc;      // 4096

// Scratch (device globals; allocation in kernel_launch is forbidden)
__device__ __align__(16) __nv_bfloat16 g_Qh[(size_t)Mr * Dm];  // [B*H][S][64]
__device__ __align__(16) __nv_bfloat16 g_Ql[(size_t)Mr * Dm];
__device__ __align__(16) __nv_bfloat16 g_Kh[(size_t)Mr * Dm];
__device__ __align__(16) __nv_bfloat16 g_Kl[(size_t)Mr * Dm];
__device__ __align__(16) __nv_bfloat16 g_Vh[(size_t)Mr * Dm];
__device__ __align__(16) __nv_bfloat16 g_Vl[(size_t)Mr * Dm];
__device__ __align__(16) __nv_bfloat16 g_Xh[(size_t)Mr * Dm];  // [M][1024]
__device__ __align__(16) __nv_bfloat16 g_Xl[(size_t)Mr * Dm];
__device__ __align__(16) __nv_bfloat16 g_Ah[(size_t)Mr * Dm];  // attn out hi/lo
__device__ __align__(16) __nv_bfloat16 g_Al[(size_t)Mr * Dm];
__device__ __align__(16) __nv_bfloat16 g_Wh[(size_t)4 * Dm * Dm];
__device__ __align__(16) __nv_bfloat16 g_Wl[(size_t)4 * Dm * Dm];

// ---------------------------------------------------------------------------
// helpers
// ---------------------------------------------------------------------------
__device__ __forceinline__ uint32_t s2u(const void* p) {
    uint32_t a;
    asm("{ .reg .u64 t; cvta.to.shared.u64 t, %1; cvt.u32.u64 %0, t; }"
        : "=r"(a) : "l"(p));
    return a;
}

__device__ __forceinline__ void cpa16(uint32_t s, const void* g) {
    asm volatile("cp.async.cg.shared.global [%0], [%1], 16;" :: "r"(s), "l"(g));
}

#define LDSM4(r0, r1, r2, r3, addr) \
    asm volatile("ldmatrix.sync.aligned.m8n8.x4.shared.b16 {%0,%1,%2,%3}, [%4];" \
        : "=r"(r0), "=r"(r1), "=r"(r2), "=r"(r3) : "r"(addr))

#define LDSM4T(r0, r1, r2, r3, addr) \
    asm volatile("ldmatrix.sync.aligned.m8n8.x4.trans.shared.b16 {%0,%1,%2,%3}, [%4];" \
        : "=r"(r0), "=r"(r1), "=r"(r2), "=r"(r3) : "r"(addr))

#define MMA_BF16(d, a, b) \
    asm volatile("mma.sync.aligned.m16n8k16.row.col.f32.bf16.bf16.f32 " \
        "{%0,%1,%2,%3}, {%4,%5,%6,%7}, {%8,%9}, {%0,%1,%2,%3};" \
        : "+f"((d)[0]), "+f"((d)[1]), "+f"((d)[2]), "+f"((d)[3]) \
        : "r"((a)[0]), "r"((a)[1]), "r"((a)[2]), "r"((a)[3]), \
          "r"((b)[0]), "r"((b)[1]))

// pack (x,y) fp32 pair -> bf16x2 hi part + bf16x2 residual (lo) part
__device__ __forceinline__ void packHL(float x, float y, uint32_t& hp, uint32_t& lp) {
    asm("cvt.rn.bf16x2.f32 %0, %1, %2;" : "=r"(hp) : "f"(y), "f"(x));
    float hx = __uint_as_float(hp << 16);
    float hy = __uint_as_float(hp & 0xFFFF0000u);
    float lx = x - hx, ly = y - hy;
    asm("cvt.rn.bf16x2.f32 %0, %1, %2;" : "=r"(lp) : "f"(ly), "f"(lx));
}

// fast 2^t on FMA pipe (t <= 0), rel err ~2e-6
__device__ __forceinline__ float fexp2(float t) {
    t = fmaxf(t, -120.f);
    float fi = rintf(t);
    float f  = t - fi;                      // [-0.5, 0.5]
    float p = 0.0013333558f;
    p = fmaf(p, f, 0.0096181291f);
    p = fmaf(p, f, 0.0555041087f);
    p = fmaf(p, f, 0.2402265070f);
    p = fmaf(p, f, 0.6931471806f);
    p = fmaf(p, f, 1.0f);
    return p * __int_as_float(((int)fi + 127) << 23);
}

// GEMM stage tile: 128 rows x 32 k (bf16), 80B pitch (64B data + 16B pad)
// -> 16B-granule index r*5+c is a full cycle mod 8: conflict-free ldmatrix.
constexpr int TPITCH  = 80;
constexpr int TILEB   = 128 * TPITCH;              // 10240 B
constexpr int STAGEB  = 4 * TILEB;
constexpr int NSTAGE  = 3;
constexpr int SMEM_SZ = 1024 + NSTAGE * STAGEB;    // 123904 B

// ---------------------------------------------------------------------------
// Split-bf16 warp-MMA GEMM: out[m,n] = sum_k A[m,k]*B[n,k] + bias[n]
// D = AhBh + AhBl + AlBh, fp32 accumulators.
// mode 0: fp32 out [M,N].  mode 1: bf16 hi/lo pair, head-split [B*H][S][64].
// ---------------------------------------------------------------------------
__global__ __launch_bounds__(256, 1) void gemm_tc(
    const __nv_bfloat16* __restrict__ Ahp, const __nv_bfloat16* __restrict__ Alp,
    const __nv_bfloat16* __restrict__ Bhp, const __nv_bfloat16* __restrict__ Blp,
    const float* __restrict__ bias, float* __restrict__ outF,
    __nv_bfloat16* __restrict__ oH, __nv_bfloat16* __restrict__ oL, int mode)
{
    extern __shared__ char smem[];
    const uint32_t sb = s2u(smem);
    const int t   = threadIdx.x;
    const int wid = t >> 5, l = t & 31;
    const int m0  = blockIdx.y * 128, n0 = blockIdx.x * 128;

    if (t < 128) ((float*)smem)[16 + t] = bias[n0 + t];

    const int lrow = t >> 2, lc = t & 3;
    const __nv_bfloat16* gA0 = Ahp + (size_t)(m0 + lrow) * Dm + lc * 8;
    const __nv_bfloat16* gA1 = Alp + (size_t)(m0 + lrow) * Dm + lc * 8;
    const __nv_bfloat16* gB0 = Bhp + (size_t)(n0 + lrow) * Dm + lc * 8;
    const __nv_bfloat16* gB1 = Blp + (size_t)(n0 + lrow) * Dm + lc * 8;
    const uint32_t so = (uint32_t)(lrow * TPITCH + lc * 16);

#define STAGE_LOAD(buf, kt)                                                     \
    {                                                                           \
        const uint32_t s0 = sb + 1024 + (buf) * STAGEB + so;                    \
        const int ke = (kt) * 32;                                               \
        cpa16(s0,                 gA0 + ke);                                    \
        cpa16(s0 + 64 * TPITCH,   gA0 + ke + 64 * Dm);                          \
        cpa16(s0 + TILEB,             gA1 + ke);                                \
        cpa16(s0 + TILEB + 64*TPITCH, gA1 + ke + 64 * Dm);                      \
        cpa16(s0 + 2*TILEB,             gB0 + ke);                              \
        cpa16(s0 + 2*TILEB + 64*TPITCH, gB0 + ke + 64 * Dm);                    \
        cpa16(s0 + 3*TILEB,             gB1 + ke);                              \
        cpa16(s0 + 3*TILEB + 64*TPITCH, gB1 + ke + 64 * Dm);                    \
        asm volatile("cp.async.commit_group;");                                 \
    }

    STAGE_LOAD(0, 0)
    STAGE_LOAD(1, 1)

    const int warp_m = (wid & 3) * 32;
    const int warp_n = (wid >> 2) * 64;
    const int arow = warp_m + (l & 7) + ((l & 8) ? 8 : 0);
    const int akb  = (l & 16) ? 1 : 0;
    const int brow = warp_n + (l & 7) + ((l & 16) ? 8 : 0);
    const int bkb  = (l >> 3) & 1;

    float acc[2][8][4] = {};

    #pragma unroll 1
    for (int kt = 0; kt < 32; kt++) {
        if (kt < 31) { asm volatile("cp.async.wait_group 1;"); }
        else         { asm volatile("cp.async.wait_group 0;"); }
        __syncthreads();
        if (kt + 2 < 32) STAGE_LOAD((kt + 2) % NSTAGE, kt + 2)

        const uint32_t st = sb + 1024 + (kt % NSTAGE) * STAGEB;
        #pragma unroll
        for (int ks = 0; ks < 2; ks++) {
            uint32_t ah[2][4], al[2][4], bh[8][2], bl[8][2];
            #pragma unroll
            for (int mt = 0; mt < 2; mt++) {
                const uint32_t ra = (uint32_t)((arow + mt * 16) * TPITCH +
                                               (ks * 2 + akb) * 16);
                LDSM4(ah[mt][0], ah[mt][1], ah[mt][2], ah[mt][3], st + ra);
                LDSM4(al[mt][0], al[mt][1], al[mt][2], al[mt][3], st + TILEB + ra);
            }
            #pragma unroll
            for (int p = 0; p < 4; p++) {
                const uint32_t rb = (uint32_t)((brow + p * 16) * TPITCH +
                                               (ks * 2 + bkb) * 16);
                LDSM4(bh[2*p][0], bh[2*p][1], bh[2*p+1][0], bh[2*p+1][1],
                      st + 2 * TILEB + rb);
                LDSM4(bl[2*p][0], bl[2*p][1], bl[2*p+1][0], bl[2*p+1][1],
                      st + 3 * TILEB + rb);
            }
            #pragma unroll
            for (int mt = 0; mt < 2; mt++)
                #pragma unroll
                for (int nt = 0; nt < 8; nt++) {
                    MMA_BF16(acc[mt][nt], ah[mt], bh[nt]);
                    MMA_BF16(acc[mt][nt], ah[mt], bl[nt]);
                    MMA_BF16(acc[mt][nt], al[mt], bh[nt]);
                }
        }
    }

    const float* bsm = (const float*)smem + 16;
    #pragma unroll
    for (int mt = 0; mt < 2; mt++) {
        #pragma unroll
        for (int nt = 0; nt < 8; nt++) {
            const int mrow = m0 + warp_m + mt * 16 + (l >> 2);
            const int ncol = n0 + warp_n + nt * 8 + (l & 3) * 2;
            const float b0 = bsm[ncol - n0], b1 = bsm[ncol - n0 + 1];
            const float v0x = acc[mt][nt][0] + b0, v0y = acc[mt][nt][1] + b1;
            const float v1x = acc[mt][nt][2] + b0, v1y = acc[mt][nt][3] + b1;
            if (mode == 1) {
                const int bb = mrow >> 11, hh = ncol >> 6, dd = ncol & 63;
                const size_t g0 = (((size_t)(bb * Hn + hh)) * Sc + (mrow & 2047)) * DKc + dd;
                uint32_t hp, lp;
                packHL(v0x, v0y, hp, lp);
                *(uint32_t*)(oH + g0) = hp;
                *(uint32_t*)(oL + g0) = lp;
                packHL(v1x, v1y, hp, lp);
                *(uint32_t*)(oH + g0 + 8 * DKc) = hp;
                *(uint32_t*)(oL + g0 + 8 * DKc) = lp;
            } else {
                float* d0 = outF + (size_t)mrow * Dm + ncol;
                *(float2*)d0 = make_float2(v0x, v0y);
                *(float2*)(d0 + 8 * Dm) = make_float2(v1x, v1y);
            }
        }
    }
#undef STAGE_LOAD
}

// ---------------------------------------------------------------------------
// fp32 -> bf16 hi/lo split
// ---------------------------------------------------------------------------
__global__ __launch_bounds__(256) void cvt_split(
    const float* __restrict__ src, __nv_bfloat16* __restrict__ hi,
    __nv_bfloat16* __restrict__ lo, int n)
{
    const int i = (blockIdx.x * blockDim.x + threadIdx.x) * 4;
    if (i >= n) return;
    float4 f = *(const float4*)(src + i);
    uint32_t h0, l0, h1, l1;
    packHL(f.x, f.y, h0, l0);
    packHL(f.z, f.w, h1, l1);
    uint32_t* H = (uint32_t*)(hi + i);
    uint32_t* L = (uint32_t*)(lo + i);
    H[0] = h0; H[1] = h1;
    L[0] = l0; L[1] = l1;
}

// ---------------------------------------------------------------------------
// Flash attention, warp-MMA bf16 hi/lo split. Causal.
// CTA: 128 q-rows (8 warps x m16) for one (b,h); key tiles of 64.
// Attention tiles: 64 rows x 64 bf16 = 128B data/row, pitch 144B
// -> granule index r*9+c ≡ r+c (mod 8): conflict-free ldmatrix.
// ---------------------------------------------------------------------------
constexpr int APITCH  = 144;
constexpr int ATILE   = 64 * APITCH;     // 9216 B per operand tile
constexpr int ASTAGE  = 4 * ATILE;       // Kh, Kl, Vh, Vl = 36864 B
constexpr int SMEM_AT = 3 * ASTAGE;      // 110592 B

__global__ __launch_bounds__(256, 1) void attn_mma(
    const __nv_bfloat16* __restrict__ Qhp, const __nv_bfloat16* __restrict__ Qlp,
    const __nv_bfloat16* __restrict__ Khp, const __nv_bfloat16* __restrict__ Klp,
    const __nv_bfloat16* __restrict__ Vhp, const __nv_bfloat16* __restrict__ Vlp,
    __nv_bfloat16* __restrict__ oH, __nv_bfloat16* __restrict__ oL)
{
    extern __shared__ char smem[];
    const uint32_t sb = s2u(smem);
    const int t = threadIdx.x, wid = t >> 5, l = t & 31;
    const int q0 = (int)(gridDim.x - 1 - blockIdx.x) * 128;   // heavy tiles first
    const int bh = blockIdx.y;
    const size_t hb = (size_t)bh * Sc * DKc;
    const int nk = q0 / 64 + 2;

    // stage-load: 512 granules (64 rows x 8) per tile; 2 per thread per tile
#define AT_LOAD(buf, jt)                                                        \
    {                                                                           \
        _Pragma("unroll")                                                       \
        for (int hf = 0; hf < 2; hf++) {                                        \
            const int idx = t + hf * 256;                                       \
            const int row = idx >> 3, cg = idx & 7;                             \
            const uint32_t s0 = sb + (buf) * ASTAGE +                           \
                                (uint32_t)(row * APITCH + cg * 16);             \
            const size_t g = hb + ((size_t)((jt) * 64 + row)) * DKc + cg * 8;   \
            cpa16(s0,             Khp + g);                                     \
            cpa16(s0 + ATILE,     Klp + g);                                     \
            cpa16(s0 + 2 * ATILE, Vhp + g);                                     \
            cpa16(s0 + 3 * ATILE, Vlp + g);                                     \
        }                                                                       \
        asm volatile("cp.async.commit_group;");                                 \
    }

    AT_LOAD(0, 0)
    AT_LOAD(1, 1)

    // Q fragments (resident)
    const int r0 = q0 + wid * 16 + (l >> 2);
    uint32_t qh[4][4], ql[4][4];
    #pragma unroll
    for (int kc = 0; kc < 4; kc++)
        #pragma unroll
        for (int r = 0; r < 4; r++) {
            const int row = r0 + ((r & 1) ? 8 : 0);
            const int d   = kc * 16 + ((r & 2) ? 8 : 0) + 2 * (l & 3);
            qh[kc][r] = __ldg((const uint32_t*)(Qhp + hb + (size_t)row * DKc + d));
            ql[kc][r] = __ldg((const uint32_t*)(Qlp + hb + (size_t)row * DKc + d));
        }

    float o[8][4] = {};
    float mr0 = -1e30f, mr1 = -1e30f, ls0 = 0.f, ls1 = 0.f;
    const float SC = 0.1803368801f;   // log2(e)/8

    #pragma unroll 1
    for (int kt = 0; kt < nk; kt++) {
        if (kt + 1 < nk) { asm volatile("cp.async.wait_group 1;"); }
        else             { asm volatile("cp.async.wait_group 0;"); }
        __syncthreads();
        if (kt + 2 < nk) AT_LOAD((kt + 2) % 3, kt + 2)

        const uint32_t st = sb + (kt % 3) * ASTAGE;
        const int jbase = kt * 64;

        // ---- S = Q K^T (3-product split) ----
        float s[8][4] = {};
        #pragma unroll
        for (int kc = 0; kc < 4; kc++) {
            uint32_t kbh[8][2], kbl[8][2];
            #pragma unroll
            for (int p = 0; p < 4; p++) {
                const uint32_t rb = st + (uint32_t)((p * 16 + (l & 7) + ((l & 16) ? 8 : 0)) * APITCH
                                                    + (kc * 2 + ((l >> 3) & 1)) * 16);
                LDSM4(kbh[2*p][0], kbh[2*p][1], kbh[2*p+1][0], kbh[2*p+1][1], rb);
                LDSM4(kbl[2*p][0], kbl[2*p][1], kbl[2*p+1][0], kbl[2*p+1][1], rb + ATILE);
            }
            #pragma unroll
            for (int nt = 0; nt < 8; nt++) {
                MMA_BF16(s[nt], qh[kc], kbh[nt]);
                MMA_BF16(s[nt], qh[kc], kbl[nt]);
                MMA_BF16(s[nt], ql[kc], kbh[nt]);
            }
        }

        // ---- causal mask (only last two tiles can cross the diagonal) ----
        if (kt >= nk - 2) {
            #pragma unroll
            for (int j = 0; j < 8; j++)
                #pragma unroll
                for (int c = 0; c < 4; c++) {
                    const int key = jbase + 8 * j + 2 * (l & 3) + (c & 1);
                    const int row = r0 + ((c & 2) ? 8 : 0);
                    if (key > row) s[j][c] = -1e30f;
                }
        }

        // ---- online softmax ----
        float m0 = -1e30f, m1 = -1e30f;
        #pragma unroll
        for (int j = 0; j < 8; j++) {
            m0 = fmaxf(m0, fmaxf(s[j][0], s[j][1]));
            m1 = fmaxf(m1, fmaxf(s[j][2], s[j][3]));
        }
        m0 = fmaxf(m0, __shfl_xor_sync(0xffffffffu, m0, 1));
        m0 = fmaxf(m0, __shfl_xor_sync(0xffffffffu, m0, 2));
        m1 = fmaxf(m1, __shfl_xor_sync(0xffffffffu, m1, 1));
        m1 = fmaxf(m1, __shfl_xor_sync(0xffffffffu, m1, 2));
        const float mn0 = fmaxf(mr0, m0), mn1 = fmaxf(mr1, m1);
        const float c0 = fexp2((mr0 - mn0) * SC), c1 = fexp2((mr1 - mn1) * SC);
        mr0 = mn0; mr1 = mn1;
        ls0 *= c0; ls1 *= c1;
        #pragma unroll
        for (int j = 0; j < 8; j++) {
            s[j][0] = fexp2((s[j][0] - mn0) * SC);
            s[j][1] = fexp2((s[j][1] - mn0) * SC);
            s[j][2] = fexp2((s[j][2] - mn1) * SC);
            s[j][3] = fexp2((s[j][3] - mn1) * SC);
            ls0 += s[j][0] + s[j][1];
            ls1 += s[j][2] + s[j][3];
            o[j][0] *= c0; o[j][1] *= c0; o[j][2] *= c1; o[j][3] *= c1;
        }

        // ---- O += P V (3-product split); P repacked from S fragments ----
        #pragma unroll
        for (int kc = 0; kc < 4; kc++) {
            uint32_t pa[4], pl[4];
            packHL(s[2*kc][0],   s[2*kc][1],   pa[0], pl[0]);
            packHL(s[2*kc][2],   s[2*kc][3],   pa[1], pl[1]);
            packHL(s[2*kc+1][0], s[2*kc+1][1], pa[2], pl[2]);
            packHL(s[2*kc+1][2], s[2*kc+1][3], pa[3], pl[3]);
            uint32_t vbh[8][2], vbl[8][2];
            #pragma unroll
            for (int p = 0; p < 4; p++) {
                const uint32_t va = st + 2 * ATILE
                    + (uint32_t)((kc * 16 + (l & 7) + ((l & 8) ? 8 : 0)) * APITCH
                                 + (p * 2 + ((l >> 4) & 1)) * 16);
                LDSM4T(vbh[2*p][0], vbh[2*p][1], vbh[2*p+1][0], vbh[2*p+1][1], va);
                LDSM4T(vbl[2*p][0], vbl[2*p][1], vbl[2*p+1][0], vbl[2*p+1][1], va + ATILE);
            }
            #pragma unroll
            for (int nt = 0; nt < 8; nt++) {
                MMA_BF16(o[nt], pa, vbh[nt]);
                MMA_BF16(o[nt], pa, vbl[nt]);
                MMA_BF16(o[nt], pl, vbh[nt]);
            }
        }
        __syncthreads();
    }

    // ---- finalize: 1/l and write bf16 hi/lo pairs into [B][S][1024] ----
    ls0 += __shfl_xor_sync(0xffffffffu, ls0, 1);
    ls0 += __shfl_xor_sync(0xffffffffu, ls0, 2);
    ls1 += __shfl_xor_sync(0xffffffffu, ls1, 1);
    ls1 += __shfl_xor_sync(0xffffffffu, ls1, 2);
    const float i0 = 1.0f / ls0, i1 = 1.0f / ls1;
    const int bb = bh >> 4, hh = bh & 15;
    #pragma unroll
    for (int j = 0; j < 8; j++) {
        const size_t g0 = ((size_t)(bb * Sc + r0)) * Dm + hh * 64 + j * 8 + 2 * (l & 3);
        uint32_t hp, lp;
        packHL(o[j][0] * i0, o[j][1] * i0, hp, lp);
        *(uint32_t*)(oH + g0) = hp;
        *(uint32_t*)(oL + g0) = lp;
        packHL(o[j][2] * i1, o[j][3] * i1, hp, lp);
        *(uint32_t*)(oH + g0 + 8 * Dm) = hp;
        *(uint32_t*)(oL + g0 + 8 * Dm) = lp;
    }
#undef AT_LOAD
}

// ---------------------------------------------------------------------------
extern "C" void kernel_launch(void* const* d_in, const int* in_sizes, int n_in,
                              void* d_out, int out_size)
{
    const float* x  = (const float*)d_in[0];
    // d_in[1] = mask (int32 tril) — causal mask hardcoded in attn_mma
    const float* Wq = (const float*)d_in[2];
    const float* bq = (const float*)d_in[3];
    const float* Wk = (const float*)d_in[4];
    const float* bk = (const float*)d_in[5];
    const float* Wv = (const float*)d_in[6];
    const float* bv = (const float*)d_in[7];
    const float* Wo = (const float*)d_in[8];
    const float* bo = (const float*)d_in[9];
    float* out = (float*)d_out;

    __nv_bfloat16 *gQh, *gQl, *gKh, *gKl, *gVh, *gVl;
    __nv_bfloat16 *gXh, *gXl, *gAh, *gAl, *gWh, *gWl;
    cudaGetSymbolAddress((void**)&gQh, g_Qh);
    cudaGetSymbolAddress((void**)&gQl, g_Ql);
    cudaGetSymbolAddress((void**)&gKh, g_Kh);
    cudaGetSymbolAddress((void**)&gKl, g_Kl);
    cudaGetSymbolAddress((void**)&gVh, g_Vh);
    cudaGetSymbolAddress((void**)&gVl, g_Vl);
    cudaGetSymbolAddress((void**)&gXh, g_Xh);
    cudaGetSymbolAddress((void**)&gXl, g_Xl);
    cudaGetSymbolAddress((void**)&gAh, g_Ah);
    cudaGetSymbolAddress((void**)&gAl, g_Al);
    cudaGetSymbolAddress((void**)&gWh, g_Wh);
    cudaGetSymbolAddress((void**)&gWl, g_Wl);

    cudaFuncSetAttribute(gemm_tc,  cudaFuncAttributeMaxDynamicSharedMemorySize, SMEM_SZ);
    cudaFuncSetAttribute(attn_mma, cudaFuncAttributeMaxDynamicSharedMemorySize, SMEM_AT);

    const int nx = Mr * Dm;       // 4M elems
    const int nw = Dm * Dm;       // 1M elems

    cvt_split<<<nx / 4 / 256, 256>>>(x,  gXh, gXl, nx);
    cvt_split<<<nw / 4 / 256, 256>>>(Wq, gWh + 0 * (size_t)nw, gWl + 0 * (size_t)nw, nw);
    cvt_split<<<nw / 4 / 256, 256>>>(Wk, gWh + 1 * (size_t)nw, gWl + 1 * (size_t)nw, nw);
    cvt_split<<<nw / 4 / 256, 256>>>(Wv, gWh + 2 * (size_t)nw, gWl + 2 * (size_t)nw, nw);
    cvt_split<<<nw / 4 / 256, 256>>>(Wo, gWh + 3 * (size_t)nw, gWl + 3 * (size_t)nw, nw);

    const dim3 gg(Dm / 128, Mr / 128);   // (8, 32)
    gemm_tc<<<gg, 256, SMEM_SZ>>>(gXh, gXl, gWh + 0 * (size_t)nw, gWl + 0 * (size_t)nw,
                                  bq, nullptr, gQh, gQl, 1);
    gemm_tc<<<gg, 256, SMEM_SZ>>>(gXh, gXl, gWh + 1 * (size_t)nw, gWl + 1 * (size_t)nw,
                                  bk, nullptr, gKh, gKl, 1);
    gemm_tc<<<gg, 256, SMEM_SZ>>>(gXh, gXl, gWh + 2 * (size_t)nw, gWl + 2 * (size_t)nw,
                                  bv, nullptr, gVh, gVl, 1);

    attn_mma<<<dim3(Sc / 128, Bc * Hn), 256, SMEM_AT>>>(gQh, gQl, gKh, gKl, gVh, gVl,
                                                        gAh, gAl);

    gemm_tc<<<gg, 256, SMEM_SZ>>>(gAh, gAl, gWh + 3 * (size_t)nw, gWl + 3 * (size_t)nw,
                                  bo, out, nullptr, nullptr, 0);
}

// round 6
// speedup vs baseline: 4.5817x; 1.3807x over previous
#include <cuda_runtime.h>
#include <cuda_fp16.h>
#include <cstdint>

// Problem constants
constexpr int Bc  = 2;
constexpr int Sc  = 2048;
constexpr int Dm  = 1024;
constexpr int Hn  = 16;
constexpr int DKc = 64;
constexpr int Mr  = Bc * Sc;      // 4096

// Scratch (device globals; allocation in kernel_launch is forbidden)
__device__ __align__(16) __half g_Qh[(size_t)Mr * Dm];  // [B*H][S][64]
__device__ __align__(16) __half g_Ql[(size_t)Mr * Dm];
__device__ __align__(16) __half g_Kh[(size_t)Mr * Dm];
__device__ __align__(16) __half g_Vh[(size_t)Mr * Dm];
__device__ __align__(16) __half g_Xh[(size_t)Mr * Dm];  // [M][1024]
__device__ __align__(16) __half g_Xl[(size_t)Mr * Dm];
__device__ __align__(16) __half g_Ah[(size_t)Mr * Dm];  // attn out hi/lo
__device__ __align__(16) __half g_Al[(size_t)Mr * Dm];
__device__ __align__(16) __half g_Wh[(size_t)4 * Dm * Dm];

// ---------------------------------------------------------------------------
// helpers
// ---------------------------------------------------------------------------
__device__ __forceinline__ uint32_t s2u(const void* p) {
    uint32_t a;
    asm("{ .reg .u64 t; cvta.to.shared.u64 t, %1; cvt.u32.u64 %0, t; }"
        : "=r"(a) : "l"(p));
    return a;
}

__device__ __forceinline__ void cpa16(uint32_t s, const void* g) {
    asm volatile("cp.async.cg.shared.global [%0], [%1], 16;" :: "r"(s), "l"(g));
}

#define LDSM4(r0, r1, r2, r3, addr) \
    asm volatile("ldmatrix.sync.aligned.m8n8.x4.shared.b16 {%0,%1,%2,%3}, [%4];" \
        : "=r"(r0), "=r"(r1), "=r"(r2), "=r"(r3) : "r"(addr))

#define LDSM4T(r0, r1, r2, r3, addr) \
    asm volatile("ldmatrix.sync.aligned.m8n8.x4.trans.shared.b16 {%0,%1,%2,%3}, [%4];" \
        : "=r"(r0), "=r"(r1), "=r"(r2), "=r"(r3) : "r"(addr))

#define MMA_F16(d, a, b) \
    asm volatile("mma.sync.aligned.m16n8k16.row.col.f32.f16.f16.f32 " \
        "{%0,%1,%2,%3}, {%4,%5,%6,%7}, {%8,%9}, {%0,%1,%2,%3};" \
        : "+f"((d)[0]), "+f"((d)[1]), "+f"((d)[2]), "+f"((d)[3]) \
        : "r"((a)[0]), "r"((a)[1]), "r"((a)[2]), "r"((a)[3]), \
          "r"((b)[0]), "r"((b)[1]))

// pack (x,y) fp32 pair -> f16x2 hi part + f16x2 residual (lo) part
__device__ __forceinline__ void packHL(float x, float y, uint32_t& hp, uint32_t& lp) {
    asm("cvt.rn.f16x2.f32 %0, %1, %2;" : "=r"(hp) : "f"(y), "f"(x));   // lo=x, hi=y
    const __half2 h2 = *reinterpret_cast<const __half2*>(&hp);
    const float hx = __low2float(h2), hy = __high2float(h2);
    const float lx = x - hx, ly = y - hy;
    asm("cvt.rn.f16x2.f32 %0, %1, %2;" : "=r"(lp) : "f"(ly), "f"(lx));
}

// fp32 pair -> single f16x2 (round only)
__device__ __forceinline__ uint32_t packH(float x, float y) {
    uint32_t hp;
    asm("cvt.rn.f16x2.f32 %0, %1, %2;" : "=r"(hp) : "f"(y), "f"(x));
    return hp;
}

// fast 2^t on FMA pipe (t <= 0), rel err ~2e-6
__device__ __forceinline__ float fexp2(float t) {
    t = fmaxf(t, -120.f);
    float fi = rintf(t);
    float f  = t - fi;                      // [-0.5, 0.5]
    float p = 0.0013333558f;
    p = fmaf(p, f, 0.0096181291f);
    p = fmaf(p, f, 0.0555041087f);
    p = fmaf(p, f, 0.2402265070f);
    p = fmaf(p, f, 0.6931471806f);
    p = fmaf(p, f, 1.0f);
    return p * __int_as_float(((int)fi + 127) << 23);
}

// GEMM stage tile: 128 rows x 32 k (f16), 80B pitch (64B data + 16B pad)
// -> 16B-granule index r*5+c is a full cycle mod 8: conflict-free ldmatrix.
constexpr int TPITCH  = 80;
constexpr int TILEB   = 128 * TPITCH;              // 10240 B
constexpr int STAGEB  = 3 * TILEB;                 // Ah, Al, Bh
constexpr int NSTAGE  = 3;
constexpr int SMEM_SZ = 1024 + NSTAGE * STAGEB;    // 93184 B

// ---------------------------------------------------------------------------
// Split-fp16 warp-MMA GEMM: out[m,n] = sum_k A[m,k]*B[n,k] + bias[n]
// D = AhBh + AlBh (A exact to fp16^2, B rounded to fp16), fp32 accumulators.
// mode 0: fp32 out [M,N].  mode 1: f16 hi(+lo if oL) head-split [B*H][S][64].
// ---------------------------------------------------------------------------
__global__ __launch_bounds__(256, 1) void gemm_tc(
    const __half* __restrict__ Ahp, const __half* __restrict__ Alp,
    const __half* __restrict__ Bhp,
    const float* __restrict__ bias, float* __restrict__ outF,
    __half* __restrict__ oH, __half* __restrict__ oL, int mode)
{
    extern __shared__ char smem[];
    const uint32_t sb = s2u(smem);
    const int t   = threadIdx.x;
    const int wid = t >> 5, l = t & 31;
    const int m0  = blockIdx.y * 128, n0 = blockIdx.x * 128;

    if (t < 128) ((float*)smem)[16 + t] = bias[n0 + t];

    const int lrow = t >> 2, lc = t & 3;
    const __half* gA0 = Ahp + (size_t)(m0 + lrow) * Dm + lc * 8;
    const __half* gA1 = Alp + (size_t)(m0 + lrow) * Dm + lc * 8;
    const __half* gB0 = Bhp + (size_t)(n0 + lrow) * Dm + lc * 8;
    const uint32_t so = (uint32_t)(lrow * TPITCH + lc * 16);

#define STAGE_LOAD(buf, kt)                                                     \
    {                                                                           \
        const uint32_t s0 = sb + 1024 + (buf) * STAGEB + so;                    \
        const int ke = (kt) * 32;                                               \
        cpa16(s0,                 gA0 + ke);                                    \
        cpa16(s0 + 64 * TPITCH,   gA0 + ke + 64 * Dm);                          \
        cpa16(s0 + TILEB,             gA1 + ke);                                \
        cpa16(s0 + TILEB + 64*TPITCH, gA1 + ke + 64 * Dm);                      \
        cpa16(s0 + 2*TILEB,             gB0 + ke);                              \
        cpa16(s0 + 2*TILEB + 64*TPITCH, gB0 + ke + 64 * Dm);                    \
        asm volatile("cp.async.commit_group;");                                 \
    }

    STAGE_LOAD(0, 0)
    STAGE_LOAD(1, 1)

    const int warp_m = (wid & 3) * 32;
    const int warp_n = (wid >> 2) * 64;
    const int arow = warp_m + (l & 7) + ((l & 8) ? 8 : 0);
    const int akb  = (l & 16) ? 1 : 0;
    const int brow = warp_n + (l & 7) + ((l & 16) ? 8 : 0);
    const int bkb  = (l >> 3) & 1;

    float acc[2][8][4] = {};

    #pragma unroll 1
    for (int kt = 0; kt < 32; kt++) {
        if (kt < 31) { asm volatile("cp.async.wait_group 1;"); }
        else         { asm volatile("cp.async.wait_group 0;"); }
        __syncthreads();
        if (kt + 2 < 32) STAGE_LOAD((kt + 2) % NSTAGE, kt + 2)

        const uint32_t st = sb + 1024 + (kt % NSTAGE) * STAGEB;
        #pragma unroll
        for (int ks = 0; ks < 2; ks++) {
            uint32_t ah[2][4], al[2][4], bh[8][2];
            #pragma unroll
            for (int mt = 0; mt < 2; mt++) {
                const uint32_t ra = (uint32_t)((arow + mt * 16) * TPITCH +
                                               (ks * 2 + akb) * 16);
                LDSM4(ah[mt][0], ah[mt][1], ah[mt][2], ah[mt][3], st + ra);
                LDSM4(al[mt][0], al[mt][1], al[mt][2], al[mt][3], st + TILEB + ra);
            }
            #pragma unroll
            for (int p = 0; p < 4; p++) {
                const uint32_t rb = (uint32_t)((brow + p * 16) * TPITCH +
                                               (ks * 2 + bkb) * 16);
                LDSM4(bh[2*p][0], bh[2*p][1], bh[2*p+1][0], bh[2*p+1][1],
                      st + 2 * TILEB + rb);
            }
            #pragma unroll
            for (int mt = 0; mt < 2; mt++)
                #pragma unroll
                for (int nt = 0; nt < 8; nt++) {
                    MMA_F16(acc[mt][nt], ah[mt], bh[nt]);
                    MMA_F16(acc[mt][nt], al[mt], bh[nt]);
                }
        }
    }

    const float* bsm = (const float*)smem + 16;
    #pragma unroll
    for (int mt = 0; mt < 2; mt++) {
        #pragma unroll
        for (int nt = 0; nt < 8; nt++) {
            const int mrow = m0 + warp_m + mt * 16 + (l >> 2);
            const int ncol = n0 + warp_n + nt * 8 + (l & 3) * 2;
            const float b0 = bsm[ncol - n0], b1 = bsm[ncol - n0 + 1];
            const float v0x = acc[mt][nt][0] + b0, v0y = acc[mt][nt][1] + b1;
            const float v1x = acc[mt][nt][2] + b0, v1y = acc[mt][nt][3] + b1;
            if (mode == 1) {
                const int bb = mrow >> 11, hh = ncol >> 6, dd = ncol & 63;
                const size_t g0 = (((size_t)(bb * Hn + hh)) * Sc + (mrow & 2047)) * DKc + dd;
                if (oL) {
                    uint32_t hp, lp;
                    packHL(v0x, v0y, hp, lp);
                    *(uint32_t*)(oH + g0) = hp;
                    *(uint32_t*)(oL + g0) = lp;
                    packHL(v1x, v1y, hp, lp);
                    *(uint32_t*)(oH + g0 + 8 * DKc) = hp;
                    *(uint32_t*)(oL + g0 + 8 * DKc) = lp;
                } else {
                    *(uint32_t*)(oH + g0)           = packH(v0x, v0y);
                    *(uint32_t*)(oH + g0 + 8 * DKc) = packH(v1x, v1y);
                }
            } else {
                float* d0 = outF + (size_t)mrow * Dm + ncol;
                *(float2*)d0 = make_float2(v0x, v0y);
                *(float2*)(d0 + 8 * Dm) = make_float2(v1x, v1y);
            }
        }
    }
#undef STAGE_LOAD
}

// ---------------------------------------------------------------------------
// fp32 -> fp16 hi/lo split (and hi-only variant)
// ---------------------------------------------------------------------------
__global__ __launch_bounds__(256) void cvt_split(
    const float* __restrict__ src, __half* __restrict__ hi,
    __half* __restrict__ lo, int n)
{
    const int i = (blockIdx.x * blockDim.x + threadIdx.x) * 4;
    if (i >= n) return;
    float4 f = *(const float4*)(src + i);
    uint32_t h0, l0, h1, l1;
    packHL(f.x, f.y, h0, l0);
    packHL(f.z, f.w, h1, l1);
    uint32_t* H = (uint32_t*)(hi + i);
    uint32_t* L = (uint32_t*)(lo + i);
    H[0] = h0; H[1] = h1;
    L[0] = l0; L[1] = l1;
}

__global__ __launch_bounds__(256) void cvt_one(
    const float* __restrict__ src, __half* __restrict__ hi, int n)
{
    const int i = (blockIdx.x * blockDim.x + threadIdx.x) * 4;
    if (i >= n) return;
    float4 f = *(const float4*)(src + i);
    uint32_t* H = (uint32_t*)(hi + i);
    H[0] = packH(f.x, f.y);
    H[1] = packH(f.z, f.w);
}

// ---------------------------------------------------------------------------
// Flash attention, warp-MMA 2-product fp16. Causal.
// CTA: 128 q-rows (8 warps x m16) for one (b,h); key tiles of 64.
// Q split hi/lo (exact); K,V rounded to fp16. P split hi/lo (exact).
// Tiles: 64 rows x 64 f16 = 128B data/row, pitch 144B
// -> granule index r*9+c ≡ r+c (mod 8): conflict-free ldmatrix.
// ---------------------------------------------------------------------------
constexpr int APITCH  = 144;
constexpr int ATILE   = 64 * APITCH;     // 9216 B per operand tile
constexpr int ASTAGE  = 2 * ATILE;       // Kh, Vh = 18432 B
constexpr int SMEM_AT = 3 * ASTAGE;      // 55296 B

__global__ __launch_bounds__(256, 1) void attn_mma(
    const __half* __restrict__ Qhp, const __half* __restrict__ Qlp,
    const __half* __restrict__ Khp, const __half* __restrict__ Vhp,
    __half* __restrict__ oH, __half* __restrict__ oL)
{
    extern __shared__ char smem[];
    const uint32_t sb = s2u(smem);
    const int t = threadIdx.x, wid = t >> 5, l = t & 31;
    const int q0 = (int)(gridDim.x - 1 - blockIdx.x) * 128;   // heavy tiles first
    const int bh = blockIdx.y;
    const size_t hb = (size_t)bh * Sc * DKc;
    const int nk = q0 / 64 + 2;

    // stage-load: 512 granules (64 rows x 8) per tile; 2 per thread per tile
#define AT_LOAD(buf, jt)                                                        \
    {                                                                           \
        _Pragma("unroll")                                                       \
        for (int hf = 0; hf < 2; hf++) {                                        \
            const int idx = t + hf * 256;                                       \
            const int row = idx >> 3, cg = idx & 7;                             \
            const uint32_t s0 = sb + (buf) * ASTAGE +                           \
                                (uint32_t)(row * APITCH + cg * 16);             \
            const size_t g = hb + ((size_t)((jt) * 64 + row)) * DKc + cg * 8;   \
            cpa16(s0,         Khp + g);                                         \
            cpa16(s0 + ATILE, Vhp + g);                                         \
        }                                                                       \
        asm volatile("cp.async.commit_group;");                                 \
    }

    AT_LOAD(0, 0)
    AT_LOAD(1, 1)

    // Q fragments (resident)
    const int r0 = q0 + wid * 16 + (l >> 2);
    uint32_t qh[4][4], ql[4][4];
    #pragma unroll
    for (int kc = 0; kc < 4; kc++)
        #pragma unroll
        for (int r = 0; r < 4; r++) {
            const int row = r0 + ((r & 1) ? 8 : 0);
            const int d   = kc * 16 + ((r & 2) ? 8 : 0) + 2 * (l & 3);
            qh[kc][r] = __ldg((const uint32_t*)(Qhp + hb + (size_t)row * DKc + d));
            ql[kc][r] = __ldg((const uint32_t*)(Qlp + hb + (size_t)row * DKc + d));
        }

    float o[8][4] = {};
    float mr0 = -1e30f, mr1 = -1e30f, ls0 = 0.f, ls1 = 0.f;
    const float SC = 0.1803368801f;   // log2(e)/8

    #pragma unroll 1
    for (int kt = 0; kt < nk; kt++) {
        if (kt + 1 < nk) { asm volatile("cp.async.wait_group 1;"); }
        else             { asm volatile("cp.async.wait_group 0;"); }
        __syncthreads();
        if (kt + 2 < nk) AT_LOAD((kt + 2) % 3, kt + 2)

        const uint32_t st = sb + (kt % 3) * ASTAGE;
        const int jbase = kt * 64;

        // ---- S = Q K^T (2-product split) ----
        float s[8][4] = {};
        #pragma unroll
        for (int kc = 0; kc < 4; kc++) {
            uint32_t kbh[8][2];
            #pragma unroll
            for (int p = 0; p < 4; p++) {
                const uint32_t rb = st + (uint32_t)((p * 16 + (l & 7) + ((l & 16) ? 8 : 0)) * APITCH
                                                    + (kc * 2 + ((l >> 3) & 1)) * 16);
                LDSM4(kbh[2*p][0], kbh[2*p][1], kbh[2*p+1][0], kbh[2*p+1][1], rb);
            }
            #pragma unroll
            for (int nt = 0; nt < 8; nt++) {
                MMA_F16(s[nt], qh[kc], kbh[nt]);
                MMA_F16(s[nt], ql[kc], kbh[nt]);
            }
        }

        // ---- causal mask (only last two tiles can cross the diagonal) ----
        if (kt >= nk - 2) {
            #pragma unroll
            for (int j = 0; j < 8; j++)
                #pragma unroll
                for (int c = 0; c < 4; c++) {
                    const int key = jbase + 8 * j + 2 * (l & 3) + (c & 1);
                    const int row = r0 + ((c & 2) ? 8 : 0);
                    if (key > row) s[j][c] = -1e30f;
                }
        }

        // ---- online softmax ----
        float m0 = -1e30f, m1 = -1e30f;
        #pragma unroll
        for (int j = 0; j < 8; j++) {
            m0 = fmaxf(m0, fmaxf(s[j][0], s[j][1]));
            m1 = fmaxf(m1, fmaxf(s[j][2], s[j][3]));
        }
        m0 = fmaxf(m0, __shfl_xor_sync(0xffffffffu, m0, 1));
        m0 = fmaxf(m0, __shfl_xor_sync(0xffffffffu, m0, 2));
        m1 = fmaxf(m1, __shfl_xor_sync(0xffffffffu, m1, 1));
        m1 = fmaxf(m1, __shfl_xor_sync(0xffffffffu, m1, 2));
        const float mn0 = fmaxf(mr0, m0), mn1 = fmaxf(mr1, m1);
        const float c0 = fexp2((mr0 - mn0) * SC), c1 = fexp2((mr1 - mn1) * SC);
        mr0 = mn0; mr1 = mn1;
        ls0 *= c0; ls1 *= c1;
        #pragma unroll
        for (int j = 0; j < 8; j++) {
            s[j][0] = fexp2((s[j][0] - mn0) * SC);
            s[j][1] = fexp2((s[j][1] - mn0) * SC);
            s[j][2] = fexp2((s[j][2] - mn1) * SC);
            s[j][3] = fexp2((s[j][3] - mn1) * SC);
            ls0 += s[j][0] + s[j][1];
            ls1 += s[j][2] + s[j][3];
            o[j][0] *= c0; o[j][1] *= c0; o[j][2] *= c1; o[j][3] *= c1;
        }

        // ---- O += P V (2-product split); P repacked from S fragments ----
        #pragma unroll
        for (int kc = 0; kc < 4; kc++) {
            uint32_t pa[4], pl[4];
            packHL(s[2*kc][0],   s[2*kc][1],   pa[0], pl[0]);
            packHL(s[2*kc][2],   s[2*kc][3],   pa[1], pl[1]);
            packHL(s[2*kc+1][0], s[2*kc+1][1], pa[2], pl[2]);
            packHL(s[2*kc+1][2], s[2*kc+1][3], pa[3], pl[3]);
            uint32_t vbh[8][2];
            #pragma unroll
            for (int p = 0; p < 4; p++) {
                const uint32_t va = st + ATILE
                    + (uint32_t)((kc * 16 + (l & 7) + ((l & 8) ? 8 : 0)) * APITCH
                                 + (p * 2 + ((l >> 4) & 1)) * 16);
                LDSM4T(vbh[2*p][0], vbh[2*p][1], vbh[2*p+1][0], vbh[2*p+1][1], va);
            }
            #pragma unroll
            for (int nt = 0; nt < 8; nt++) {
                MMA_F16(o[nt], pa, vbh[nt]);
                MMA_F16(o[nt], pl, vbh[nt]);
            }
        }
        __syncthreads();
    }

    // ---- finalize: 1/l and write f16 hi/lo pairs into [B][S][1024] ----
    ls0 += __shfl_xor_sync(0xffffffffu, ls0, 1);
    ls0 += __shfl_xor_sync(0xffffffffu, ls0, 2);
    ls1 += __shfl_xor_sync(0xffffffffu, ls1, 1);
    ls1 += __shfl_xor_sync(0xffffffffu, ls1, 2);
    const float i0 = 1.0f / ls0, i1 = 1.0f / ls1;
    const int bb = bh >> 4, hh = bh & 15;
    #pragma unroll
    for (int j = 0; j < 8; j++) {
        const size_t g0 = ((size_t)(bb * Sc + r0)) * Dm + hh * 64 + j * 8 + 2 * (l & 3);
        uint32_t hp, lp;
        packHL(o[j][0] * i0, o[j][1] * i0, hp, lp);
        *(uint32_t*)(oH + g0) = hp;
        *(uint32_t*)(oL + g0) = lp;
        packHL(o[j][2] * i1, o[j][3] * i1, hp, lp);
        *(uint32_t*)(oH + g0 + 8 * Dm) = hp;
        *(uint32_t*)(oL + g0 + 8 * Dm) = lp;
    }
#undef AT_LOAD
}

// ---------------------------------------------------------------------------
extern "C" void kernel_launch(void* const* d_in, const int* in_sizes, int n_in,
                              void* d_out, int out_size)
{
    const float* x  = (const float*)d_in[0];
    // d_in[1] = mask (int32 tril) — causal mask hardcoded in attn_mma
    const float* Wq = (const float*)d_in[2];
    const float* bq = (const float*)d_in[3];
    const float* Wk = (const float*)d_in[4];
    const float* bk = (const float*)d_in[5];
    const float* Wv = (const float*)d_in[6];
    const float* bv = (const float*)d_in[7];
    const float* Wo = (const float*)d_in[8];
    const float* bo = (const float*)d_in[9];
    float* out = (float*)d_out;

    __half *gQh, *gQl, *gKh, *gVh, *gXh, *gXl, *gAh, *gAl, *gWh;
    cudaGetSymbolAddress((void**)&gQh, g_Qh);
    cudaGetSymbolAddress((void**)&gQl, g_Ql);
    cudaGetSymbolAddress((void**)&gKh, g_Kh);
    cudaGetSymbolAddress((void**)&gVh, g_Vh);
    cudaGetSymbolAddress((void**)&gXh, g_Xh);
    cudaGetSymbolAddress((void**)&gXl, g_Xl);
    cudaGetSymbolAddress((void**)&gAh, g_Ah);
    cudaGetSymbolAddress((void**)&gAl, g_Al);
    cudaGetSymbolAddress((void**)&gWh, g_Wh);

    cudaFuncSetAttribute(gemm_tc,  cudaFuncAttributeMaxDynamicSharedMemorySize, SMEM_SZ);
    cudaFuncSetAttribute(attn_mma, cudaFuncAttributeMaxDynamicSharedMemorySize, SMEM_AT);

    const int nx = Mr * Dm;       // 4M elems
    const int nw = Dm * Dm;       // 1M elems

    cvt_split<<<nx / 4 / 256, 256>>>(x, gXh, gXl, nx);
    cvt_one<<<nw / 4 / 256, 256>>>(Wq, gWh + 0 * (size_t)nw, nw);
    cvt_one<<<nw / 4 / 256, 256>>>(Wk, gWh + 1 * (size_t)nw, nw);
    cvt_one<<<nw / 4 / 256, 256>>>(Wv, gWh + 2 * (size_t)nw, nw);
    cvt_one<<<nw / 4 / 256, 256>>>(Wo, gWh + 3 * (size_t)nw, nw);

    const dim3 gg(Dm / 128, Mr / 128);   // (8, 32)
    gemm_tc<<<gg, 256, SMEM_SZ>>>(gXh, gXl, gWh + 0 * (size_t)nw,
                                  bq, nullptr, gQh, gQl, 1);
    gemm_tc<<<gg, 256, SMEM_SZ>>>(gXh, gXl, gWh + 1 * (size_t)nw,
                                  bk, nullptr, gKh, nullptr, 1);
    gemm_tc<<<gg, 256, SMEM_SZ>>>(gXh, gXl, gWh + 2 * (size_t)nw,
                                  bv, nullptr, gVh, nullptr, 1);

    attn_mma<<<dim3(Sc / 128, Bc * Hn), 256, SMEM_AT>>>(gQh, gQl, gKh, gVh, gAh, gAl);

    gemm_tc<<<gg, 256, SMEM_SZ>>>(gAh, gAl, gWh + 3 * (size_t)nw,
                                  bo, out, nullptr, nullptr, 0);
}

// round 7
// speedup vs baseline: 5.7349x; 1.2517x over previous
#include <cuda_runtime.h>
#include <cuda_fp16.h>
#include <cstdint>

// Problem constants
constexpr int Bc  = 2;
constexpr int Sc  = 2048;
constexpr int Dm  = 1024;
constexpr int Hn  = 16;
constexpr int DKc = 64;
constexpr int Mr  = Bc * Sc;      // 4096

// Scratch (device globals; allocation in kernel_launch is forbidden)
__device__ __align__(16) __half g_Qh[(size_t)Mr * Dm];  // [B*H][S][64]
__device__ __align__(16) __half g_Kh[(size_t)Mr * Dm];
__device__ __align__(16) __half g_Vh[(size_t)Mr * Dm];
__device__ __align__(16) __half g_Xh[(size_t)Mr * Dm];  // [M][1024] fp16 round
__device__ __align__(16) __half g_Ah[(size_t)Mr * Dm];  // attn out hi/lo
__device__ __align__(16) __half g_Al[(size_t)Mr * Dm];
__device__ __align__(16) __half g_Wh[(size_t)4 * Dm * Dm];

// ---------------------------------------------------------------------------
// helpers
// ---------------------------------------------------------------------------
__device__ __forceinline__ uint32_t s2u(const void* p) {
    uint32_t a;
    asm("{ .reg .u64 t; cvta.to.shared.u64 t, %1; cvt.u32.u64 %0, t; }"
        : "=r"(a) : "l"(p));
    return a;
}

__device__ __forceinline__ void cpa16(uint32_t s, const void* g) {
    asm volatile("cp.async.cg.shared.global [%0], [%1], 16;" :: "r"(s), "l"(g));
}

#define LDSM4(r0, r1, r2, r3, addr) \
    asm volatile("ldmatrix.sync.aligned.m8n8.x4.shared.b16 {%0,%1,%2,%3}, [%4];" \
        : "=r"(r0), "=r"(r1), "=r"(r2), "=r"(r3) : "r"(addr))

#define LDSM4T(r0, r1, r2, r3, addr) \
    asm volatile("ldmatrix.sync.aligned.m8n8.x4.trans.shared.b16 {%0,%1,%2,%3}, [%4];" \
        : "=r"(r0), "=r"(r1), "=r"(r2), "=r"(r3) : "r"(addr))

#define MMA_F16(d, a, b) \
    asm volatile("mma.sync.aligned.m16n8k16.row.col.f32.f16.f16.f32 " \
        "{%0,%1,%2,%3}, {%4,%5,%6,%7}, {%8,%9}, {%0,%1,%2,%3};" \
        : "+f"((d)[0]), "+f"((d)[1]), "+f"((d)[2]), "+f"((d)[3]) \
        : "r"((a)[0]), "r"((a)[1]), "r"((a)[2]), "r"((a)[3]), \
          "r"((b)[0]), "r"((b)[1]))

// pack (x,y) fp32 pair -> f16x2 hi part + f16x2 residual (lo) part
__device__ __forceinline__ void packHL(float x, float y, uint32_t& hp, uint32_t& lp) {
    asm("cvt.rn.f16x2.f32 %0, %1, %2;" : "=r"(hp) : "f"(y), "f"(x));   // lo=x, hi=y
    const __half2 h2 = *reinterpret_cast<const __half2*>(&hp);
    const float hx = __low2float(h2), hy = __high2float(h2);
    const float lx = x - hx, ly = y - hy;
    asm("cvt.rn.f16x2.f32 %0, %1, %2;" : "=r"(lp) : "f"(ly), "f"(lx));
}

// fp32 pair -> single f16x2 (round only)
__device__ __forceinline__ uint32_t packH(float x, float y) {
    uint32_t hp;
    asm("cvt.rn.f16x2.f32 %0, %1, %2;" : "=r"(hp) : "f"(y), "f"(x));
    return hp;
}

// fast 2^t on FMA pipe (t <= 0), rel err ~2e-6
__device__ __forceinline__ float fexp2(float t) {
    t = fmaxf(t, -120.f);
    float fi = rintf(t);
    float f  = t - fi;                      // [-0.5, 0.5]
    float p = 0.0013333558f;
    p = fmaf(p, f, 0.0096181291f);
    p = fmaf(p, f, 0.0555041087f);
    p = fmaf(p, f, 0.2402265070f);
    p = fmaf(p, f, 0.6931471806f);
    p = fmaf(p, f, 1.0f);
    return p * __int_as_float(((int)fi + 127) << 23);
}

// GEMM stage tile: 128 rows x 32 k (f16), 80B pitch (64B data + 16B pad)
// -> 16B-granule index r*5+c is a full cycle mod 8: conflict-free ldmatrix.
constexpr int TPITCH  = 80;
constexpr int TILEB   = 128 * TPITCH;              // 10240 B
constexpr int NSTAGE  = 3;
// stage = (NPROD A tiles) + 1 B tile
constexpr int SMEM_G1 = 1024 + NSTAGE * 2 * TILEB; // 62464 B
constexpr int SMEM_G2 = 1024 + NSTAGE * 3 * TILEB; // 93184 B

// ---------------------------------------------------------------------------
// Split-fp16 warp-MMA GEMM: out[m,n] = sum_k A[m,k]*B[n,k] + bias[n]
// NPROD=1: D = Ah·Bh.  NPROD=2: D = Ah·Bh + Al·Bh.  fp32 accumulators.
// mode 0: fp32 out [M,N].  mode 1: f16 hi(+lo if oL) head-split [B*H][S][64].
// ---------------------------------------------------------------------------
template <int NPROD>
__global__ __launch_bounds__(256, 1) void gemm_tc(
    const __half* __restrict__ Ahp, const __half* __restrict__ Alp,
    const __half* __restrict__ Bhp,
    const float* __restrict__ bias, float* __restrict__ outF,
    __half* __restrict__ oH, __half* __restrict__ oL, int mode)
{
    constexpr int STAGEB = (NPROD + 1) * TILEB;
    constexpr int BOFF   = NPROD * TILEB;
    extern __shared__ char smem[];
    const uint32_t sb = s2u(smem);
    const int t   = threadIdx.x;
    const int wid = t >> 5, l = t & 31;
    const int m0  = blockIdx.y * 128, n0 = blockIdx.x * 128;

    if (t < 128) ((float*)smem)[16 + t] = bias[n0 + t];

    const int lrow = t >> 2, lc = t & 3;
    const __half* gA0 = Ahp + (size_t)(m0 + lrow) * Dm + lc * 8;
    const __half* gA1 = (NPROD == 2) ? (Alp + (size_t)(m0 + lrow) * Dm + lc * 8) : nullptr;
    const __half* gB0 = Bhp + (size_t)(n0 + lrow) * Dm + lc * 8;
    const uint32_t so = (uint32_t)(lrow * TPITCH + lc * 16);

#define STAGE_LOAD(buf, kt)                                                     \
    {                                                                           \
        const uint32_t s0 = sb + 1024 + (buf) * STAGEB + so;                    \
        const int ke = (kt) * 32;                                               \
        cpa16(s0,                 gA0 + ke);                                    \
        cpa16(s0 + 64 * TPITCH,   gA0 + ke + 64 * Dm);                          \
        if (NPROD == 2) {                                                       \
            cpa16(s0 + TILEB,             gA1 + ke);                            \
            cpa16(s0 + TILEB + 64*TPITCH, gA1 + ke + 64 * Dm);                  \
        }                                                                       \
        cpa16(s0 + BOFF,             gB0 + ke);                                 \
        cpa16(s0 + BOFF + 64*TPITCH, gB0 + ke + 64 * Dm);                       \
        asm volatile("cp.async.commit_group;");                                 \
    }

    STAGE_LOAD(0, 0)
    STAGE_LOAD(1, 1)

    const int warp_m = (wid & 3) * 32;
    const int warp_n = (wid >> 2) * 64;
    const int arow = warp_m + (l & 7) + ((l & 8) ? 8 : 0);
    const int akb  = (l & 16) ? 1 : 0;
    const int brow = warp_n + (l & 7) + ((l & 16) ? 8 : 0);
    const int bkb  = (l >> 3) & 1;

    float acc[2][8][4] = {};

    #pragma unroll 1
    for (int kt = 0; kt < 32; kt++) {
        if (kt < 31) { asm volatile("cp.async.wait_group 1;"); }
        else         { asm volatile("cp.async.wait_group 0;"); }
        __syncthreads();
        if (kt + 2 < 32) STAGE_LOAD((kt + 2) % NSTAGE, kt + 2)

        const uint32_t st = sb + 1024 + (kt % NSTAGE) * STAGEB;
        #pragma unroll
        for (int ks = 0; ks < 2; ks++) {
            uint32_t ah[2][4], al[2][4], bh[8][2];
            #pragma unroll
            for (int mt = 0; mt < 2; mt++) {
                const uint32_t ra = (uint32_t)((arow + mt * 16) * TPITCH +
                                               (ks * 2 + akb) * 16);
                LDSM4(ah[mt][0], ah[mt][1], ah[mt][2], ah[mt][3], st + ra);
                if (NPROD == 2)
                    LDSM4(al[mt][0], al[mt][1], al[mt][2], al[mt][3], st + TILEB + ra);
            }
            #pragma unroll
            for (int p = 0; p < 4; p++) {
                const uint32_t rb = (uint32_t)((brow + p * 16) * TPITCH +
                                               (ks * 2 + bkb) * 16);
                LDSM4(bh[2*p][0], bh[2*p][1], bh[2*p+1][0], bh[2*p+1][1],
                      st + BOFF + rb);
            }
            #pragma unroll
            for (int mt = 0; mt < 2; mt++)
                #pragma unroll
                for (int nt = 0; nt < 8; nt++) {
                    MMA_F16(acc[mt][nt], ah[mt], bh[nt]);
                    if (NPROD == 2) MMA_F16(acc[mt][nt], al[mt], bh[nt]);
                }
        }
    }

    const float* bsm = (const float*)smem + 16;
    #pragma unroll
    for (int mt = 0; mt < 2; mt++) {
        #pragma unroll
        for (int nt = 0; nt < 8; nt++) {
            const int mrow = m0 + warp_m + mt * 16 + (l >> 2);
            const int ncol = n0 + warp_n + nt * 8 + (l & 3) * 2;
            const float b0 = bsm[ncol - n0], b1 = bsm[ncol - n0 + 1];
            const float v0x = acc[mt][nt][0] + b0, v0y = acc[mt][nt][1] + b1;
            const float v1x = acc[mt][nt][2] + b0, v1y = acc[mt][nt][3] + b1;
            if (mode == 1) {
                const int bb = mrow >> 11, hh = ncol >> 6, dd = ncol & 63;
                const size_t g0 = (((size_t)(bb * Hn + hh)) * Sc + (mrow & 2047)) * DKc + dd;
                if (oL) {
                    uint32_t hp, lp;
                    packHL(v0x, v0y, hp, lp);
                    *(uint32_t*)(oH + g0) = hp;
                    *(uint32_t*)(oL + g0) = lp;
                    packHL(v1x, v1y, hp, lp);
                    *(uint32_t*)(oH + g0 + 8 * DKc) = hp;
                    *(uint32_t*)(oL + g0 + 8 * DKc) = lp;
                } else {
                    *(uint32_t*)(oH + g0)           = packH(v0x, v0y);
                    *(uint32_t*)(oH + g0 + 8 * DKc) = packH(v1x, v1y);
                }
            } else {
                float* d0 = outF + (size_t)mrow * Dm + ncol;
                *(float2*)d0 = make_float2(v0x, v0y);
                *(float2*)(d0 + 8 * Dm) = make_float2(v1x, v1y);
            }
        }
    }
#undef STAGE_LOAD
}

// ---------------------------------------------------------------------------
// fp32 -> fp16 round (x), and 4-weight variant (one launch)
// ---------------------------------------------------------------------------
__global__ __launch_bounds__(256) void cvt_one(
    const float* __restrict__ src, __half* __restrict__ hi, int n)
{
    const int i = (blockIdx.x * blockDim.x + threadIdx.x) * 4;
    if (i >= n) return;
    float4 f = *(const float4*)(src + i);
    uint32_t* H = (uint32_t*)(hi + i);
    H[0] = packH(f.x, f.y);
    H[1] = packH(f.z, f.w);
}

__global__ __launch_bounds__(256) void cvt_w4(
    const float* __restrict__ w0, const float* __restrict__ w1,
    const float* __restrict__ w2, const float* __restrict__ w3,
    __half* __restrict__ hi, int n)
{
    const float* src = (blockIdx.y == 0) ? w0 : (blockIdx.y == 1) ? w1
                     : (blockIdx.y == 2) ? w2 : w3;
    const int i = (blockIdx.x * blockDim.x + threadIdx.x) * 4;
    if (i >= n) return;
    float4 f = *(const float4*)(src + i);
    uint32_t* H = (uint32_t*)(hi + (size_t)blockIdx.y * n + i);
    H[0] = packH(f.x, f.y);
    H[1] = packH(f.z, f.w);
}

// ---------------------------------------------------------------------------
// Flash attention, warp-MMA fp16. Causal.
// CTA: 128 q-rows (8 warps x m16) for one (b,h); key tiles of 64.
// Q,K,V rounded fp16 (S single product); P split hi/lo (PV 2 products).
// Tiles: 64 rows x 64 f16 = 128B data/row, pitch 144B
// -> granule index r*9+c ≡ r+c (mod 8): conflict-free ldmatrix.
// ---------------------------------------------------------------------------
constexpr int APITCH  = 144;
constexpr int ATILE   = 64 * APITCH;     // 9216 B per operand tile
constexpr int ASTAGE  = 2 * ATILE;       // Kh, Vh = 18432 B
constexpr int SMEM_AT = 3 * ASTAGE;      // 55296 B

__global__ __launch_bounds__(256, 1) void attn_mma(
    const __half* __restrict__ Qhp,
    const __half* __restrict__ Khp, const __half* __restrict__ Vhp,
    __half* __restrict__ oH, __half* __restrict__ oL)
{
    extern __shared__ char smem[];
    const uint32_t sb = s2u(smem);
    const int t = threadIdx.x, wid = t >> 5, l = t & 31;
    const int q0 = (int)(gridDim.x - 1 - blockIdx.x) * 128;   // heavy tiles first
    const int bh = blockIdx.y;
    const size_t hb = (size_t)bh * Sc * DKc;
    const int nk = q0 / 64 + 2;

    // stage-load: 512 granules (64 rows x 8) per tile; 2 per thread per tile
#define AT_LOAD(buf, jt)                                                        \
    {                                                                           \
        _Pragma("unroll")                                                       \
        for (int hf = 0; hf < 2; hf++) {                                        \
            const int idx = t + hf * 256;                                       \
            const int row = idx >> 3, cg = idx & 7;                             \
            const uint32_t s0 = sb + (buf) * ASTAGE +                           \
                                (uint32_t)(row * APITCH + cg * 16);             \
            const size_t g = hb + ((size_t)((jt) * 64 + row)) * DKc + cg * 8;   \
            cpa16(s0,         Khp + g);                                         \
            cpa16(s0 + ATILE, Vhp + g);                                         \
        }                                                                       \
        asm volatile("cp.async.commit_group;");                                 \
    }

    AT_LOAD(0, 0)
    AT_LOAD(1, 1)

    // Q fragments (resident)
    const int r0 = q0 + wid * 16 + (l >> 2);
    uint32_t qh[4][4];
    #pragma unroll
    for (int kc = 0; kc < 4; kc++)
        #pragma unroll
        for (int r = 0; r < 4; r++) {
            const int row = r0 + ((r & 1) ? 8 : 0);
            const int d   = kc * 16 + ((r & 2) ? 8 : 0) + 2 * (l & 3);
            qh[kc][r] = __ldg((const uint32_t*)(Qhp + hb + (size_t)row * DKc + d));
        }

    float o[8][4] = {};
    float mr0 = -1e30f, mr1 = -1e30f, ls0 = 0.f, ls1 = 0.f;
    const float SC = 0.1803368801f;   // log2(e)/8

    #pragma unroll 1
    for (int kt = 0; kt < nk; kt++) {
        if (kt + 1 < nk) { asm volatile("cp.async.wait_group 1;"); }
        else             { asm volatile("cp.async.wait_group 0;"); }
        __syncthreads();
        if (kt + 2 < nk) AT_LOAD((kt + 2) % 3, kt + 2)

        const uint32_t st = sb + (kt % 3) * ASTAGE;
        const int jbase = kt * 64;

        // ---- S = Q K^T (single product) ----
        float s[8][4] = {};
        #pragma unroll
        for (int kc = 0; kc < 4; kc++) {
            uint32_t kbh[8][2];
            #pragma unroll
            for (int p = 0; p < 4; p++) {
                const uint32_t rb = st + (uint32_t)((p * 16 + (l & 7) + ((l & 16) ? 8 : 0)) * APITCH
                                                    + (kc * 2 + ((l >> 3) & 1)) * 16);
                LDSM4(kbh[2*p][0], kbh[2*p][1], kbh[2*p+1][0], kbh[2*p+1][1], rb);
            }
            #pragma unroll
            for (int nt = 0; nt < 8; nt++)
                MMA_F16(s[nt], qh[kc], kbh[nt]);
        }

        // ---- causal mask (only last two tiles can cross the diagonal) ----
        if (kt >= nk - 2) {
            #pragma unroll
            for (int j = 0; j < 8; j++)
                #pragma unroll
                for (int c = 0; c < 4; c++) {
                    const int key = jbase + 8 * j + 2 * (l & 3) + (c & 1);
                    const int row = r0 + ((c & 2) ? 8 : 0);
                    if (key > row) s[j][c] = -1e30f;
                }
        }

        // ---- online softmax ----
        float m0 = -1e30f, m1 = -1e30f;
        #pragma unroll
        for (int j = 0; j < 8; j++) {
            m0 = fmaxf(m0, fmaxf(s[j][0], s[j][1]));
            m1 = fmaxf(m1, fmaxf(s[j][2], s[j][3]));
        }
        m0 = fmaxf(m0, __shfl_xor_sync(0xffffffffu, m0, 1));
        m0 = fmaxf(m0, __shfl_xor_sync(0xffffffffu, m0, 2));
        m1 = fmaxf(m1, __shfl_xor_sync(0xffffffffu, m1, 1));
        m1 = fmaxf(m1, __shfl_xor_sync(0xffffffffu, m1, 2));
        const float mn0 = fmaxf(mr0, m0), mn1 = fmaxf(mr1, m1);
        const float c0 = fexp2((mr0 - mn0) * SC), c1 = fexp2((mr1 - mn1) * SC);
        mr0 = mn0; mr1 = mn1;
        ls0 *= c0; ls1 *= c1;
        #pragma unroll
        for (int j = 0; j < 8; j++) {
            s[j][0] = fexp2((s[j][0] - mn0) * SC);
            s[j][1] = fexp2((s[j][1] - mn0) * SC);
            s[j][2] = fexp2((s[j][2] - mn1) * SC);
            s[j][3] = fexp2((s[j][3] - mn1) * SC);
            ls0 += s[j][0] + s[j][1];
            ls1 += s[j][2] + s[j][3];
            o[j][0] *= c0; o[j][1] *= c0; o[j][2] *= c1; o[j][3] *= c1;
        }

        // ---- O += P V (2-product split); P repacked from S fragments ----
        #pragma unroll
        for (int kc = 0; kc < 4; kc++) {
            uint32_t pa[4], pl[4];
            packHL(s[2*kc][0],   s[2*kc][1],   pa[0], pl[0]);
            packHL(s[2*kc][2],   s[2*kc][3],   pa[1], pl[1]);
            packHL(s[2*kc+1][0], s[2*kc+1][1], pa[2], pl[2]);
            packHL(s[2*kc+1][2], s[2*kc+1][3], pa[3], pl[3]);
            uint32_t vbh[8][2];
            #pragma unroll
            for (int p = 0; p < 4; p++) {
                const uint32_t va = st + ATILE
                    + (uint32_t)((kc * 16 + (l & 7) + ((l & 8) ? 8 : 0)) * APITCH
                                 + (p * 2 + ((l >> 4) & 1)) * 16);
                LDSM4T(vbh[2*p][0], vbh[2*p][1], vbh[2*p+1][0], vbh[2*p+1][1], va);
            }
            #pragma unroll
            for (int nt = 0; nt < 8; nt++) {
                MMA_F16(o[nt], pa, vbh[nt]);
                MMA_F16(o[nt], pl, vbh[nt]);
            }
        }
        __syncthreads();
    }

    // ---- finalize: 1/l and write f16 hi/lo pairs into [B][S][1024] ----
    ls0 += __shfl_xor_sync(0xffffffffu, ls0, 1);
    ls0 += __shfl_xor_sync(0xffffffffu, ls0, 2);
    ls1 += __shfl_xor_sync(0xffffffffu, ls1, 1);
    ls1 += __shfl_xor_sync(0xffffffffu, ls1, 2);
    const float i0 = 1.0f / ls0, i1 = 1.0f / ls1;
    const int bb = bh >> 4, hh = bh & 15;
    #pragma unroll
    for (int j = 0; j < 8; j++) {
        const size_t g0 = ((size_t)(bb * Sc + r0)) * Dm + hh * 64 + j * 8 + 2 * (l & 3);
        uint32_t hp, lp;
        packHL(o[j][0] * i0, o[j][1] * i0, hp, lp);
        *(uint32_t*)(oH + g0) = hp;
        *(uint32_t*)(oL + g0) = lp;
        packHL(o[j][2] * i1, o[j][3] * i1, hp, lp);
        *(uint32_t*)(oH + g0 + 8 * Dm) = hp;
        *(uint32_t*)(oL + g0 + 8 * Dm) = lp;
    }
#undef AT_LOAD
}

// ---------------------------------------------------------------------------
extern "C" void kernel_launch(void* const* d_in, const int* in_sizes, int n_in,
                              void* d_out, int out_size)
{
    const float* x  = (const float*)d_in[0];
    // d_in[1] = mask (int32 tril) — causal mask hardcoded in attn_mma
    const float* Wq = (const float*)d_in[2];
    const float* bq = (const float*)d_in[3];
    const float* Wk = (const float*)d_in[4];
    const float* bk = (const float*)d_in[5];
    const float* Wv = (const float*)d_in[6];
    const float* bv = (const float*)d_in[7];
    const float* Wo = (const float*)d_in[8];
    const float* bo = (const float*)d_in[9];
    float* out = (float*)d_out;

    __half *gQh, *gKh, *gVh, *gXh, *gAh, *gAl, *gWh;
    cudaGetSymbolAddress((void**)&gQh, g_Qh);
    cudaGetSymbolAddress((void**)&gKh, g_Kh);
    cudaGetSymbolAddress((void**)&gVh, g_Vh);
    cudaGetSymbolAddress((void**)&gXh, g_Xh);
    cudaGetSymbolAddress((void**)&gAh, g_Ah);
    cudaGetSymbolAddress((void**)&gAl, g_Al);
    cudaGetSymbolAddress((void**)&gWh, g_Wh);

    cudaFuncSetAttribute(gemm_tc<1>, cudaFuncAttributeMaxDynamicSharedMemorySize, SMEM_G1);
    cudaFuncSetAttribute(gemm_tc<2>, cudaFuncAttributeMaxDynamicSharedMemorySize, SMEM_G2);
    cudaFuncSetAttribute(attn_mma,   cudaFuncAttributeMaxDynamicSharedMemorySize, SMEM_AT);

    const int nx = Mr * Dm;       // 4M elems
    const int nw = Dm * Dm;       // 1M elems

    cvt_one<<<nx / 4 / 256, 256>>>(x, gXh, nx);
    cvt_w4<<<dim3(nw / 4 / 256, 4), 256>>>(Wq, Wk, Wv, Wo, gWh, nw);

    const dim3 gg(Dm / 128, Mr / 128);   // (8, 32)
    gemm_tc<1><<<gg, 256, SMEM_G1>>>(gXh, nullptr, gWh + 0 * (size_t)nw,
                                     bq, nullptr, gQh, nullptr, 1);
    gemm_tc<1><<<gg, 256, SMEM_G1>>>(gXh, nullptr, gWh + 1 * (size_t)nw,
                                     bk, nullptr, gKh, nullptr, 1);
    gemm_tc<1><<<gg, 256, SMEM_G1>>>(gXh, nullptr, gWh + 2 * (size_t)nw,
                                     bv, nullptr, gVh, nullptr, 1);

    attn_mma<<<dim3(Sc / 128, Bc * Hn), 256, SMEM_AT>>>(gQh, gKh, gVh, gAh, gAl);

    gemm_tc<2><<<gg, 256, SMEM_G2>>>(gAh, gAl, gWh + 3 * (size_t)nw,
                                     bo, out, nullptr, nullptr, 0);
}

// round 8
// speedup vs baseline: 6.7823x; 1.1826x over previous
#include <cuda_runtime.h>
#include <cuda_fp16.h>
#include <cstdint>

// Problem constants
constexpr int Bc  = 2;
constexpr int Sc  = 2048;
constexpr int Dm  = 1024;
constexpr int Hn  = 16;
constexpr int DKc = 64;
constexpr int Mr  = Bc * Sc;      // 4096

// Scratch (device globals; allocation in kernel_launch is forbidden)
__device__ __align__(16) __half g_Qh[(size_t)Mr * Dm];  // [B*H][S][64]
__device__ __align__(16) __half g_Kh[(size_t)Mr * Dm];
__device__ __align__(16) __half g_Vh[(size_t)Mr * Dm];
__device__ __align__(16) __half g_Xh[(size_t)Mr * Dm];  // [M][1024] fp16 round
__device__ __align__(16) __half g_Ah[(size_t)Mr * Dm];  // attn out hi/lo
__device__ __align__(16) __half g_Al[(size_t)Mr * Dm];
__device__ __align__(16) __half g_Wh[(size_t)4 * Dm * Dm];

// ---------------------------------------------------------------------------
// helpers
// ---------------------------------------------------------------------------
__device__ __forceinline__ uint32_t s2u(const void* p) {
    uint32_t a;
    asm("{ .reg .u64 t; cvta.to.shared.u64 t, %1; cvt.u32.u64 %0, t; }"
        : "=r"(a) : "l"(p));
    return a;
}

__device__ __forceinline__ void cpa16(uint32_t s, const void* g) {
    asm volatile("cp.async.cg.shared.global [%0], [%1], 16;" :: "r"(s), "l"(g));
}

#define LDSM4(r0, r1, r2, r3, addr) \
    asm volatile("ldmatrix.sync.aligned.m8n8.x4.shared.b16 {%0,%1,%2,%3}, [%4];" \
        : "=r"(r0), "=r"(r1), "=r"(r2), "=r"(r3) : "r"(addr))

#define LDSM4T(r0, r1, r2, r3, addr) \
    asm volatile("ldmatrix.sync.aligned.m8n8.x4.trans.shared.b16 {%0,%1,%2,%3}, [%4];" \
        : "=r"(r0), "=r"(r1), "=r"(r2), "=r"(r3) : "r"(addr))

#define MMA_F16(d, a, b) \
    asm volatile("mma.sync.aligned.m16n8k16.row.col.f32.f16.f16.f32 " \
        "{%0,%1,%2,%3}, {%4,%5,%6,%7}, {%8,%9}, {%0,%1,%2,%3};" \
        : "+f"((d)[0]), "+f"((d)[1]), "+f"((d)[2]), "+f"((d)3[0-3]), "+f"((d)[3]) \
        : )
#undef MMA_F16
#define MMA_F16(d, a, b) \
    asm volatile("mma.sync.aligned.m16n8k16.row.col.f32.f16.f16.f32 " \
        "{%0,%1,%2,%3}, {%4,%5,%6,%7}, {%8,%9}, {%0,%1,%2,%3};" \
        : "+f"((d)[0]), "+f"((d)[1]), "+f"((d)[2]), "+f"((d)[3]) \
        : "r"((a)[0]), "r"((a)[1]), "r"((a)[2]), "r"((a)[3]), \
          "r"((b)[0]), "r"((b)[1]))

// pack (x,y) fp32 pair -> f16x2 hi part + f16x2 residual (lo) part
__device__ __forceinline__ void packHL(float x, float y, uint32_t& hp, uint32_t& lp) {
    asm("cvt.rn.f16x2.f32 %0, %1, %2;" : "=r"(hp) : "f"(y), "f"(x));   // lo=x, hi=y
    const __half2 h2 = *reinterpret_cast<const __half2*>(&hp);
    const float hx = __low2float(h2), hy = __high2float(h2);
    const float lx = x - hx, ly = y - hy;
    asm("cvt.rn.f16x2.f32 %0, %1, %2;" : "=r"(lp) : "f"(ly), "f"(lx));
}

// fp32 pair -> single f16x2 (round only)
__device__ __forceinline__ uint32_t packH(float x, float y) {
    uint32_t hp;
    asm("cvt.rn.f16x2.f32 %0, %1, %2;" : "=r"(hp) : "f"(y), "f"(x));
    return hp;
}

// fast 2^t on FMA pipe (t <= 0), rel err ~2e-6
__device__ __forceinline__ float fexp2(float t) {
    t = fmaxf(t, -120.f);
    float fi = rintf(t);
    float f  = t - fi;                      // [-0.5, 0.5]
    float p = 0.0013333558f;
    p = fmaf(p, f, 0.0096181291f);
    p = fmaf(p, f, 0.0555041087f);
    p = fmaf(p, f, 0.2402265070f);
    p = fmaf(p, f, 0.6931471806f);
    p = fmaf(p, f, 1.0f);
    return p * __int_as_float(((int)fi + 127) << 23);
}

// GEMM stage tile: 128 rows x 32 k (f16), 80B pitch (64B data + 16B pad)
// -> 16B-granule index r*5+c is a full cycle mod 8: conflict-free ldmatrix.
constexpr int TPITCH  = 80;
constexpr int TILEB   = 128 * TPITCH;              // 10240 B
constexpr int NSTAGE  = 3;
constexpr int SMEM_G1 = 1024 + NSTAGE * 2 * TILEB; // 62464 B  (A + B per stage)
constexpr int SMEM_G2 = 1024 + NSTAGE * 3 * TILEB; // 93184 B  (Ah + Al + B)

// ---------------------------------------------------------------------------
// Fused QKV GEMM (single-product fp16): grid (24, 32).
// wsel = blockIdx.x/8 selects {Wq,Wk,Wv}; output head-split f16.
// ---------------------------------------------------------------------------
__global__ __launch_bounds__(256, 2) void gemm_qkv(
    const __half* __restrict__ Xh, const __half* __restrict__ Wbase,
    const float* __restrict__ bq, const float* __restrict__ bk,
    const float* __restrict__ bv,
    __half* __restrict__ oQ, __half* __restrict__ oK, __half* __restrict__ oV)
{
    constexpr int STAGEB = 2 * TILEB;
    extern __shared__ char smem[];
    const uint32_t sb = s2u(smem);
    const int t   = threadIdx.x;
    const int wid = t >> 5, l = t & 31;
    const int wsel = blockIdx.x >> 3;
    const int n0  = (blockIdx.x & 7) * 128, m0 = blockIdx.y * 128;

    const float* bias = (wsel == 0) ? bq : (wsel == 1) ? bk : bv;
    __half* oH        = (wsel == 0) ? oQ : (wsel == 1) ? oK : oV;
    const __half* Bhp = Wbase + (size_t)wsel * Dm * Dm;

    if (t < 128) ((float*)smem)[16 + t] = bias[n0 + t];

    const int lrow = t >> 2, lc = t & 3;
    const __half* gA0 = Xh  + (size_t)(m0 + lrow) * Dm + lc * 8;
    const __half* gB0 = Bhp + (size_t)(n0 + lrow) * Dm + lc * 8;
    const uint32_t so = (uint32_t)(lrow * TPITCH + lc * 16);

#define STAGE_LOAD(buf, kt)                                                     \
    {                                                                           \
        const uint32_t s0 = sb + 1024 + (buf) * STAGEB + so;                    \
        const int ke = (kt) * 32;                                               \
        cpa16(s0,                 gA0 + ke);                                    \
        cpa16(s0 + 64 * TPITCH,   gA0 + ke + 64 * Dm);                          \
        cpa16(s0 + TILEB,             gB0 + ke);                                \
        cpa16(s0 + TILEB + 64*TPITCH, gB0 + ke + 64 * Dm);                      \
        asm volatile("cp.async.commit_group;");                                 \
    }

    STAGE_LOAD(0, 0)
    STAGE_LOAD(1, 1)

    const int warp_m = (wid & 3) * 32;
    const int warp_n = (wid >> 2) * 64;
    const int arow = warp_m + (l & 7) + ((l & 8) ? 8 : 0);
    const int akb  = (l & 16) ? 1 : 0;
    const int brow = warp_n + (l & 7) + ((l & 16) ? 8 : 0);
    const int bkb  = (l >> 3) & 1;

    float acc[2][8][4] = {};

    #pragma unroll 1
    for (int kt = 0; kt < 32; kt++) {
        if (kt < 31) { asm volatile("cp.async.wait_group 1;"); }
        else         { asm volatile("cp.async.wait_group 0;"); }
        __syncthreads();
        if (kt + 2 < 32) STAGE_LOAD((kt + 2) % NSTAGE, kt + 2)

        const uint32_t st = sb + 1024 + (kt % NSTAGE) * STAGEB;
        #pragma unroll
        for (int ks = 0; ks < 2; ks++) {
            uint32_t ah[2][4], bh[8][2];
            #pragma unroll
            for (int mt = 0; mt < 2; mt++) {
                const uint32_t ra = (uint32_t)((arow + mt * 16) * TPITCH +
                                               (ks * 2 + akb) * 16);
                LDSM4(ah[mt][0], ah[mt][1], ah[mt][2], ah[mt][3], st + ra);
            }
            #pragma unroll
            for (int p = 0; p < 4; p++) {
                const uint32_t rb = (uint32_t)((brow + p * 16) * TPITCH +
                                               (ks * 2 + bkb) * 16);
                LDSM4(bh[2*p][0], bh[2*p][1], bh[2*p+1][0], bh[2*p+1][1],
                      st + TILEB + rb);
            }
            #pragma unroll
            for (int mt = 0; mt < 2; mt++)
                #pragma unroll
                for (int nt = 0; nt < 8; nt++)
                    MMA_F16(acc[mt][nt], ah[mt], bh[nt]);
        }
    }

    const float* bsm = (const float*)smem + 16;
    #pragma unroll
    for (int mt = 0; mt < 2; mt++) {
        #pragma unroll
        for (int nt = 0; nt < 8; nt++) {
            const int mrow = m0 + warp_m + mt * 16 + (l >> 2);
            const int ncol = n0 + warp_n + nt * 8 + (l & 3) * 2;
            const float b0 = bsm[ncol - n0], b1 = bsm[ncol - n0 + 1];
            const int bb = mrow >> 11, hh = ncol >> 6, dd = ncol & 63;
            const size_t g0 = (((size_t)(bb * Hn + hh)) * Sc + (mrow & 2047)) * DKc + dd;
            *(uint32_t*)(oH + g0)           = packH(acc[mt][nt][0] + b0, acc[mt][nt][1] + b1);
            *(uint32_t*)(oH + g0 + 8 * DKc) = packH(acc[mt][nt][2] + b0, acc[mt][nt][3] + b1);
        }
    }
#undef STAGE_LOAD
}

// ---------------------------------------------------------------------------
// Output GEMM (2-product fp16 split A): D = Ah·B + Al·B + bias, fp32 out.
// ---------------------------------------------------------------------------
__global__ __launch_bounds__(256, 2) void gemm_wo(
    const __half* __restrict__ Ahp, const __half* __restrict__ Alp,
    const __half* __restrict__ Bhp,
    const float* __restrict__ bias, float* __restrict__ outF)
{
    constexpr int STAGEB = 3 * TILEB;
    constexpr int BOFF   = 2 * TILEB;
    extern __shared__ char smem[];
    const uint32_t sb = s2u(smem);
    const int t   = threadIdx.x;
    const int wid = t >> 5, l = t & 31;
    const int m0  = blockIdx.y * 128, n0 = blockIdx.x * 128;

    if (t < 128) ((float*)smem)[16 + t] = bias[n0 + t];

    const int lrow = t >> 2, lc = t & 3;
    const __half* gA0 = Ahp + (size_t)(m0 + lrow) * Dm + lc * 8;
    const __half* gA1 = Alp + (size_t)(m0 + lrow) * Dm + lc * 8;
    const __half* gB0 = Bhp + (size_t)(n0 + lrow) * Dm + lc * 8;
    const uint32_t so = (uint32_t)(lrow * TPITCH + lc * 16);

#define STAGE_LOAD(buf, kt)                                                     \
    {                                                                           \
        const uint32_t s0 = sb + 1024 + (buf) * STAGEB + so;                    \
        const int ke = (kt) * 32;                                               \
        cpa16(s0,                 gA0 + ke);                                    \
        cpa16(s0 + 64 * TPITCH,   gA0 + ke + 64 * Dm);                          \
        cpa16(s0 + TILEB,             gA1 + ke);                                \
        cpa16(s0 + TILEB + 64*TPITCH, gA1 + ke + 64 * Dm);                      \
        cpa16(s0 + BOFF,             gB0 + ke);                                 \
        cpa16(s0 + BOFF + 64*TPITCH, gB0 + ke + 64 * Dm);                       \
        asm volatile("cp.async.commit_group;");                                 \
    }

    STAGE_LOAD(0, 0)
    STAGE_LOAD(1, 1)

    const int warp_m = (wid & 3) * 32;
    const int warp_n = (wid >> 2) * 64;
    const int arow = warp_m + (l & 7) + ((l & 8) ? 8 : 0);
    const int akb  = (l & 16) ? 1 : 0;
    const int brow = warp_n + (l & 7) + ((l & 16) ? 8 : 0);
    const int bkb  = (l >> 3) & 1;

    float acc[2][8][4] = {};

    #pragma unroll 1
    for (int kt = 0; kt < 32; kt++) {
        if (kt < 31) { asm volatile("cp.async.wait_group 1;"); }
        else         { asm volatile("cp.async.wait_group 0;"); }
        __syncthreads();
        if (kt + 2 < 32) STAGE_LOAD((kt + 2) % NSTAGE, kt + 2)

        const uint32_t st = sb + 1024 + (kt % NSTAGE) * STAGEB;
        #pragma unroll
        for (int ks = 0; ks < 2; ks++) {
            uint32_t ah[2][4], al[2][4], bh[8][2];
            #pragma unroll
            for (int mt = 0; mt < 2; mt++) {
                const uint32_t ra = (uint32_t)((arow + mt * 16) * TPITCH +
                                               (ks * 2 + akb) * 16);
                LDSM4(ah[mt][0], ah[mt][1], ah[mt][2], ah[mt][3], st + ra);
                LDSM4(al[mt][0], al[mt][1], al[mt][2], al[mt][3], st + TILEB + ra);
            }
            #pragma unroll
            for (int p = 0; p < 4; p++) {
                const uint32_t rb = (uint32_t)((brow + p * 16) * TPITCH +
                                               (ks * 2 + bkb) * 16);
                LDSM4(bh[2*p][0], bh[2*p][1], bh[2*p+1][0], bh[2*p+1][1],
                      st + BOFF + rb);
            }
            #pragma unroll
            for (int mt = 0; mt < 2; mt++)
                #pragma unroll
                for (int nt = 0; nt < 8; nt++) {
                    MMA_F16(acc[mt][nt], ah[mt], bh[nt]);
                    MMA_F16(acc[mt][nt], al[mt], bh[nt]);
                }
        }
    }

    const float* bsm = (const float*)smem + 16;
    #pragma unroll
    for (int mt = 0; mt < 2; mt++) {
        #pragma unroll
        for (int nt = 0; nt < 8; nt++) {
            const int mrow = m0 + warp_m + mt * 16 + (l >> 2);
            const int ncol = n0 + warp_n + nt * 8 + (l & 3) * 2;
            const float b0 = bsm[ncol - n0], b1 = bsm[ncol - n0 + 1];
            float* d0 = outF + (size_t)mrow * Dm + ncol;
            *(float2*)d0 = make_float2(acc[mt][nt][0] + b0, acc[mt][nt][1] + b1);
            *(float2*)(d0 + 8 * Dm) = make_float2(acc[mt][nt][2] + b0, acc[mt][nt][3] + b1);
        }
    }
#undef STAGE_LOAD
}

// ---------------------------------------------------------------------------
// Fused fp32 -> fp16 conversion: y = 0..3 -> weights (n elems each),
// y = 4..7 -> x in 4 chunks of n.
// ---------------------------------------------------------------------------
__global__ __launch_bounds__(256) void cvt_all(
    const float* __restrict__ w0, const float* __restrict__ w1,
    const float* __restrict__ w2, const float* __restrict__ w3,
    const float* __restrict__ x,
    __half* __restrict__ wh, __half* __restrict__ xh, int n)
{
    const int y = blockIdx.y;
    const int i = (blockIdx.x * blockDim.x + threadIdx.x) * 4;
    if (i >= n) return;
    const float* src;
    __half* dst;
    if (y < 4) {
        src = (y == 0) ? w0 : (y == 1) ? w1 : (y == 2) ? w2 : w3;
        dst = wh + (size_t)y * n;
    } else {
        src = x + (size_t)(y - 4) * n;
        dst = xh + (size_t)(y - 4) * n;
    }
    float4 f = *(const float4*)(src + i);
    uint32_t* H = (uint32_t*)(dst + i);
    H[0] = packH(f.x, f.y);
    H[1] = packH(f.z, f.w);
}

// ---------------------------------------------------------------------------
// Flash attention, warp-MMA fp16. Causal.
// CTA: 128 q-rows (8 warps x m16) for one (b,h); key tiles of 64.
// Q,K,V rounded fp16 (S single product); P split hi/lo (PV 2 products).
// Tiles: 64 rows x 64 f16 = 128B data/row, pitch 144B
// -> granule index r*9+c ≡ r+c (mod 8): conflict-free ldmatrix.
// ---------------------------------------------------------------------------
constexpr int APITCH  = 144;
constexpr int ATILE   = 64 * APITCH;     // 9216 B per operand tile
constexpr int ASTAGE  = 2 * ATILE;       // Kh, Vh = 18432 B
constexpr int SMEM_AT = 3 * ASTAGE;      // 55296 B

__global__ __launch_bounds__(256, 1) void attn_mma(
    const __half* __restrict__ Qhp,
    const __half* __restrict__ Khp, const __half* __restrict__ Vhp,
    __half* __restrict__ oH, __half* __restrict__ oL)
{
    extern __shared__ char smem[];
    const uint32_t sb = s2u(smem);
    const int t = threadIdx.x, wid = t >> 5, l = t & 31;
    const int q0 = (int)(gridDim.x - 1 - blockIdx.x) * 128;   // heavy tiles first
    const int bh = blockIdx.y;
    const size_t hb = (size_t)bh * Sc * DKc;
    const int nk = q0 / 64 + 2;

    // stage-load: 512 granules (64 rows x 8) per tile; 2 per thread per tile
#define AT_LOAD(buf, jt)                                                        \
    {                                                                           \
        _Pragma("unroll")                                                       \
        for (int hf = 0; hf < 2; hf++) {                                        \
            const int idx = t + hf * 256;                                       \
            const int row = idx >> 3, cg = idx & 7;                             \
            const uint32_t s0 = sb + (buf) * ASTAGE +                           \
                                (uint32_t)(row * APITCH + cg * 16);             \
            const size_t g = hb + ((size_t)((jt) * 64 + row)) * DKc + cg * 8;   \
            cpa16(s0,         Khp + g);                                         \
            cpa16(s0 + ATILE, Vhp + g);                                         \
        }                                                                       \
        asm volatile("cp.async.commit_group;");                                 \
    }

    AT_LOAD(0, 0)
    AT_LOAD(1, 1)

    // Q fragments (resident)
    const int r0 = q0 + wid * 16 + (l >> 2);
    uint32_t qh[4][4];
    #pragma unroll
    for (int kc = 0; kc < 4; kc++)
        #pragma unroll
        for (int r = 0; r < 4; r++) {
            const int row = r0 + ((r & 1) ? 8 : 0);
            const int d   = kc * 16 + ((r & 2) ? 8 : 0) + 2 * (l & 3);
            qh[kc][r] = __ldg((const uint32_t*)(Qhp + hb + (size_t)row * DKc + d));
        }

    float o[8][4] = {};
    float mr0 = -1e30f, mr1 = -1e30f, ls0 = 0.f, ls1 = 0.f;
    const float SC = 0.1803368801f;   // log2(e)/8

    #pragma unroll 1
    for (int kt = 0; kt < nk; kt++) {
        if (kt + 1 < nk) { asm volatile("cp.async.wait_group 1;"); }
        else             { asm volatile("cp.async.wait_group 0;"); }
        __syncthreads();
        if (kt + 2 < nk) AT_LOAD((kt + 2) % 3, kt + 2)

        const uint32_t st = sb + (kt % 3) * ASTAGE;
        const int jbase = kt * 64;

        // ---- S = Q K^T (single product) ----
        float s[8][4] = {};
        #pragma unroll
        for (int kc = 0; kc < 4; kc++) {
            uint32_t kbh[8][2];
            #pragma unroll
            for (int p = 0; p < 4; p++) {
                const uint32_t rb = st + (uint32_t)((p * 16 + (l & 7) + ((l & 16) ? 8 : 0)) * APITCH
                                                    + (kc * 2 + ((l >> 3) & 1)) * 16);
                LDSM4(kbh[2*p][0], kbh[2*p][1], kbh[2*p+1][0], kbh[2*p+1][1], rb);
            }
            #pragma unroll
            for (int nt = 0; nt < 8; nt++)
                MMA_F16(s[nt], qh[kc], kbh[nt]);
        }

        // ---- causal mask (only last two tiles can cross the diagonal) ----
        if (kt >= nk - 2) {
            #pragma unroll
            for (int j = 0; j < 8; j++)
                #pragma unroll
                for (int c = 0; c < 4; c++) {
                    const int key = jbase + 8 * j + 2 * (l & 3) + (c & 1);
                    const int row = r0 + ((c & 2) ? 8 : 0);
                    if (key > row) s[j][c] = -1e30f;
                }
        }

        // ---- online softmax ----
        float m0 = -1e30f, m1 = -1e30f;
        #pragma unroll
        for (int j = 0; j < 8; j++) {
            m0 = fmaxf(m0, fmaxf(s[j][0], s[j][1]));
            m1 = fmaxf(m1, fmaxf(s[j][2], s[j][3]));
        }
        m0 = fmaxf(m0, __shfl_xor_sync(0xffffffffu, m0, 1));
        m0 = fmaxf(m0, __shfl_xor_sync(0xffffffffu, m0, 2));
        m1 = fmaxf(m1, __shfl_xor_sync(0xffffffffu, m1, 1));
        m1 = fmaxf(m1, __shfl_xor_sync(0xffffffffu, m1, 2));
        const float mn0 = fmaxf(mr0, m0), mn1 = fmaxf(mr1, m1);
        const float c0 = fexp2((mr0 - mn0) * SC), c1 = fexp2((mr1 - mn1) * SC);
        mr0 = mn0; mr1 = mn1;
        ls0 *= c0; ls1 *= c1;
        #pragma unroll
        for (int j = 0; j < 8; j++) {
            s[j][0] = fexp2((s[j][0] - mn0) * SC);
            s[j][1] = fexp2((s[j][1] - mn0) * SC);
            s[j][2] = fexp2((s[j][2] - mn1) * SC);
            s[j][3] = fexp2((s[j][3] - mn1) * SC);
            ls0 += s[j][0] + s[j][1];
            ls1 += s[j][2] + s[j][3];
            o[j][0] *= c0; o[j][1] *= c0; o[j][2] *= c1; o[j][3] *= c1;
        }

        // ---- O += P V (2-product split); P repacked from S fragments ----
        #pragma unroll
        for (int kc = 0; kc < 4; kc++) {
            uint32_t pa[4], pl[4];
            packHL(s[2*kc][0],   s[2*kc][1],   pa[0], pl[0]);
            packHL(s[2*kc][2],   s[2*kc][3],   pa[1], pl[1]);
            packHL(s[2*kc+1][0], s[2*kc+1][1], pa[2], pl[2]);
            packHL(s[2*kc+1][2], s[2*kc+1][3], pa[3], pl[3]);
            uint32_t vbh[8][2];
            #pragma unroll
            for (int p = 0; p < 4; p++) {
                const uint32_t va = st + ATILE
                    + (uint32_t)((kc * 16 + (l & 7) + ((l & 8) ? 8 : 0)) * APITCH
                                 + (p * 2 + ((l >> 4) & 1)) * 16);
                LDSM4T(vbh[2*p][0], vbh[2*p][1], vbh[2*p+1][0], vbh[2*p+1][1], va);
            }
            #pragma unroll
            for (int nt = 0; nt < 8; nt++) {
                MMA_F16(o[nt], pa, vbh[nt]);
                MMA_F16(o[nt], pl, vbh[nt]);
            }
        }
        __syncthreads();
    }

    // ---- finalize: 1/l and write f16 hi/lo pairs into [B][S][1024] ----
    ls0 += __shfl_xor_sync(0xffffffffu, ls0, 1);
    ls0 += __shfl_xor_sync(0xffffffffu, ls0, 2);
    ls1 += __shfl_xor_sync(0xffffffffu, ls1, 1);
    ls1 += __shfl_xor_sync(0xffffffffu, ls1, 2);
    const float i0 = 1.0f / ls0, i1 = 1.0f / ls1;
    const int bb = bh >> 4, hh = bh & 15;
    #pragma unroll
    for (int j = 0; j < 8; j++) {
        const size_t g0 = ((size_t)(bb * Sc + r0)) * Dm + hh * 64 + j * 8 + 2 * (l & 3);
        uint32_t hp, lp;
        packHL(o[j][0] * i0, o[j][1] * i0, hp, lp);
        *(uint32_t*)(oH + g0) = hp;
        *(uint32_t*)(oL + g0) = lp;
        packHL(o[j][2] * i1, o[j][3] * i1, hp, lp);
        *(uint32_t*)(oH + g0 + 8 * Dm) = hp;
        *(uint32_t*)(oL + g0 + 8 * Dm) = lp;
    }
#undef AT_LOAD
}

// ---------------------------------------------------------------------------
extern "C" void kernel_launch(void* const* d_in, const int* in_sizes, int n_in,
                              void* d_out, int out_size)
{
    const float* x  = (const float*)d_in[0];
    // d_in[1] = mask (int32 tril) — causal mask hardcoded in attn_mma
    const float* Wq = (const float*)d_in[2];
    const float* bq = (const float*)d_in[3];
    const float* Wk = (const float*)d_in[4];
    const float* bk = (const float*)d_in[5];
    const float* Wv = (const float*)d_in[6];
    const float* bv = (const float*)d_in[7];
    const float* Wo = (const float*)d_in[8];
    const float* bo = (const float*)d_in[9];
    float* out = (float*)d_out;

    __half *gQh, *gKh, *gVh, *gXh, *gAh, *gAl, *gWh;
    cudaGetSymbolAddress((void**)&gQh, g_Qh);
    cudaGetSymbolAddress((void**)&gKh, g_Kh);
    cudaGetSymbolAddress((void**)&gVh, g_Vh);
    cudaGetSymbolAddress((void**)&gXh, g_Xh);
    cudaGetSymbolAddress((void**)&gAh, g_Ah);
    cudaGetSymbolAddress((void**)&gAl, g_Al);
    cudaGetSymbolAddress((void**)&gWh, g_Wh);

    cudaFuncSetAttribute(gemm_qkv, cudaFuncAttributeMaxDynamicSharedMemorySize, SMEM_G1);
    cudaFuncSetAttribute(gemm_wo,  cudaFuncAttributeMaxDynamicSharedMemorySize, SMEM_G2);
    cudaFuncSetAttribute(attn_mma, cudaFuncAttributeMaxDynamicSharedMemorySize, SMEM_AT);

    const int nw = Dm * Dm;       // 1M elems

    cvt_all<<<dim3(nw / 4 / 256, 8), 256>>>(Wq, Wk, Wv, Wo, x, gWh, gXh, nw);

    gemm_qkv<<<dim3(24, 32), 256, SMEM_G1>>>(gXh, gWh, bq, bk, bv, gQh, gKh, gVh);

    attn_mma<<<dim3(Sc / 128, Bc * Hn), 256, SMEM_AT>>>(gQh, gKh, gVh, gAh, gAl);

    gemm_wo<<<dim3(8, 32), 256, SMEM_G2>>>(gAh, gAl, gWh + 3 * (size_t)nw, bo, out);
}